// round 1
// baseline (speedup 1.0000x reference)
#include <cuda_runtime.h>

typedef unsigned long long u64;

// ---- packed f32x2 helpers (FFMA2 path: only reachable via PTX fma.rn.f32x2) ----
__device__ __forceinline__ u64 pk2(float lo, float hi) {
    u64 r; asm("mov.b64 %0,{%1,%2};" : "=l"(r) : "f"(lo), "f"(hi)); return r;
}
__device__ __forceinline__ float2 upk2(u64 v) {
    float2 f; asm("mov.b64 {%0,%1},%2;" : "=f"(f.x), "=f"(f.y) : "l"(v)); return f;
}
__device__ __forceinline__ u64 fma2(u64 a, u64 b, u64 c) {
    u64 d; asm("fma.rn.f32x2 %0,%1,%2,%3;" : "=l"(d) : "l"(a), "l"(b), "l"(c)); return d;
}
__device__ __forceinline__ u64 add2(u64 a, u64 b) {
    u64 d; asm("add.rn.f32x2 %0,%1,%2;" : "=l"(d) : "l"(a), "l"(b)); return d;
}

#define ROWS 4
#define TPB  128

__global__ __launch_bounds__(TPB, 2)
void fused_decoder_kernel(const float4* __restrict__ x4,
                          const float*  __restrict__ w1,
                          const float*  __restrict__ g1,
                          const float*  __restrict__ b1,
                          const float*  __restrict__ w2,
                          const float*  __restrict__ g2,
                          const float*  __restrict__ b2,
                          const float*  __restrict__ w3,
                          const float*  __restrict__ b3,
                          const int*    __restrict__ Bp,
                          float*        __restrict__ out,
                          int N)
{
    // ---- stage all weights in shared memory ----
    __shared__ __align__(16) float sw1[64 * 32];   // 8 KB, row-major [k][j]
    __shared__ __align__(16) float sw2[32 * 16];   // 2 KB, row-major [k][j]
    __shared__ float sw3[16 * 3];
    __shared__ float sg1[32], sb1[32], sg2[16], sb2[16], sb3[3];

    const int tid = threadIdx.x;
    for (int i = tid; i < 2048; i += TPB) sw1[i] = w1[i];
    for (int i = tid; i < 512;  i += TPB) sw2[i] = w2[i];
    if (tid < 48) sw3[tid] = w3[tid];
    if (tid < 32) { sg1[tid] = g1[tid]; sb1[tid] = b1[tid]; }
    if (tid < 16) { sg2[tid] = g2[tid]; sb2[tid] = b2[tid]; }
    if (tid < 3)  sb3[tid] = b3[tid];
    __syncthreads();

    const u64* __restrict__ w1p = reinterpret_cast<const u64*>(sw1); // [k][jp] pairs
    const u64* __restrict__ w2p = reinterpret_cast<const u64*>(sw2);

    const int base = (blockIdx.x * TPB + tid) * ROWS;
    if (base >= N) return;

    const int Bv = __ldg(Bp);
    const int HW = N / Bv;   // pixels per image

    // ---- layer 1: h1 = x @ w1, accumulated as 16 packed j-pairs per row ----
    u64 acc[ROWS][16];
    #pragma unroll
    for (int r = 0; r < ROWS; r++)
        #pragma unroll
        for (int jp = 0; jp < 16; jp++) acc[r][jp] = 0ull;  // (+0.f, +0.f)

    float curf[ROWS][4];
    #pragma unroll
    for (int r = 0; r < ROWS; r++) {
        int rr = base + r; if (rr > N - 1) rr = N - 1;   // clamp (safety; N%4==0 here)
        float4 t = x4[rr * 16];
        curf[r][0] = t.x; curf[r][1] = t.y; curf[r][2] = t.z; curf[r][3] = t.w;
    }

    #pragma unroll 1
    for (int kc = 0; kc < 16; kc++) {
        // prefetch next 4-float chunk per row
        float nxtf[ROWS][4];
        if (kc < 15) {
            #pragma unroll
            for (int r = 0; r < ROWS; r++) {
                int rr = base + r; if (rr > N - 1) rr = N - 1;
                float4 t = x4[rr * 16 + kc + 1];
                nxtf[r][0] = t.x; nxtf[r][1] = t.y; nxtf[r][2] = t.z; nxtf[r][3] = t.w;
            }
        } else {
            #pragma unroll
            for (int r = 0; r < ROWS; r++)
                #pragma unroll
                for (int q = 0; q < 4; q++) nxtf[r][q] = 0.0f;
        }

        #pragma unroll
        for (int kk = 0; kk < 4; kk++) {
            u64 xd[ROWS];
            #pragma unroll
            for (int r = 0; r < ROWS; r++) xd[r] = pk2(curf[r][kk], curf[r][kk]);
            const u64* wrow = w1p + (kc * 4 + kk) * 16;
            #pragma unroll
            for (int jp = 0; jp < 16; jp++) {
                u64 w = wrow[jp];                 // LDS.64 broadcast, shared by 4 rows
                #pragma unroll
                for (int r = 0; r < ROWS; r++)
                    acc[r][jp] = fma2(xd[r], w, acc[r][jp]);
            }
        }

        #pragma unroll
        for (int r = 0; r < ROWS; r++)
            #pragma unroll
            for (int q = 0; q < 4; q++) curf[r][q] = nxtf[r][q];
    }

    // ---- per-row epilogue: LN1 -> ReLU -> L2 -> LN2 -> ReLU -> L3 -> normalize ----
    #pragma unroll
    for (int r = 0; r < ROWS; r++) {
        const int row = base + r;
        if (row < N) {
            // LayerNorm over 32
            u64 s = acc[r][0];
            #pragma unroll
            for (int jp = 1; jp < 16; jp++) s = add2(s, acc[r][jp]);
            float2 sf = upk2(s);
            const float mean = (sf.x + sf.y) * (1.0f / 32.0f);
            u64 q = 0ull;
            #pragma unroll
            for (int jp = 0; jp < 16; jp++) q = fma2(acc[r][jp], acc[r][jp], q);
            float2 qf = upk2(q);
            const float var = (qf.x + qf.y) * (1.0f / 32.0f) - mean * mean;
            const float sc  = rsqrtf(var + 1e-5f);
            const float nms = -mean * sc;

            float h1[32];
            #pragma unroll
            for (int jp = 0; jp < 16; jp++) {
                float2 v = upk2(acc[r][jp]);
                float v0 = fmaf(v.x, sc, nms);
                float v1 = fmaf(v.y, sc, nms);
                v0 = fmaf(v0, sg1[2 * jp],     sb1[2 * jp]);
                v1 = fmaf(v1, sg1[2 * jp + 1], sb1[2 * jp + 1]);
                h1[2 * jp]     = fmaxf(v0, 0.0f);
                h1[2 * jp + 1] = fmaxf(v1, 0.0f);
            }

            // layer 2: 32 -> 16, 8 packed j-pairs
            u64 a2[8];
            #pragma unroll
            for (int jp = 0; jp < 8; jp++) a2[jp] = 0ull;
            #pragma unroll
            for (int k2 = 0; k2 < 32; k2++) {
                u64 hd = pk2(h1[k2], h1[k2]);
                const u64* wrow = w2p + k2 * 8;
                #pragma unroll
                for (int jp = 0; jp < 8; jp++)
                    a2[jp] = fma2(hd, wrow[jp], a2[jp]);
            }

            // LayerNorm over 16
            u64 s2 = a2[0];
            #pragma unroll
            for (int jp = 1; jp < 8; jp++) s2 = add2(s2, a2[jp]);
            float2 s2f = upk2(s2);
            const float mean2 = (s2f.x + s2f.y) * (1.0f / 16.0f);
            u64 q2 = 0ull;
            #pragma unroll
            for (int jp = 0; jp < 8; jp++) q2 = fma2(a2[jp], a2[jp], q2);
            float2 q2f = upk2(q2);
            const float var2 = (q2f.x + q2f.y) * (1.0f / 16.0f) - mean2 * mean2;
            const float sc2  = rsqrtf(var2 + 1e-5f);
            const float nms2 = -mean2 * sc2;

            float h2[16];
            #pragma unroll
            for (int jp = 0; jp < 8; jp++) {
                float2 v = upk2(a2[jp]);
                float v0 = fmaf(v.x, sc2, nms2);
                float v1 = fmaf(v.y, sc2, nms2);
                v0 = fmaf(v0, sg2[2 * jp],     sb2[2 * jp]);
                v1 = fmaf(v1, sg2[2 * jp + 1], sb2[2 * jp + 1]);
                h2[2 * jp]     = fmaxf(v0, 0.0f);
                h2[2 * jp + 1] = fmaxf(v1, 0.0f);
            }

            // layer 3: 16 -> 3 (+bias)
            float o0 = sb3[0], o1 = sb3[1], o2 = sb3[2];
            #pragma unroll
            for (int k3 = 0; k3 < 16; k3++) {
                const float h = h2[k3];
                o0 = fmaf(h, sw3[k3 * 3 + 0], o0);
                o1 = fmaf(h, sw3[k3 * 3 + 1], o1);
                o2 = fmaf(h, sw3[k3 * 3 + 2], o2);
            }

            // F.normalize along channel dim (3-vector)
            const float nn  = sqrtf(o0 * o0 + o1 * o1 + o2 * o2);
            const float inv = 1.0f / fmaxf(nn, 1e-12f);

            // scatter to [B, 3, H, W]
            const int b  = row / HW;
            const int hw = row - b * HW;
            const int ob = (b * 3) * HW + hw;
            out[ob]          = o0 * inv;
            out[ob + HW]     = o1 * inv;
            out[ob + 2 * HW] = o2 * inv;
        }
    }
}

extern "C" void kernel_launch(void* const* d_in, const int* in_sizes, int n_in,
                              void* d_out, int out_size)
{
    const float* x  = (const float*)d_in[0];
    const float* w1 = (const float*)d_in[1];
    const float* g1 = (const float*)d_in[2];
    const float* b1 = (const float*)d_in[3];
    const float* w2 = (const float*)d_in[4];
    const float* g2 = (const float*)d_in[5];
    const float* b2 = (const float*)d_in[6];
    const float* w3 = (const float*)d_in[7];
    const float* b3 = (const float*)d_in[8];
    const int*   Bp = (const int*)d_in[9];

    const int N = in_sizes[0] / 64;
    const int threads_needed = (N + ROWS - 1) / ROWS;
    const int blocks = (threads_needed + TPB - 1) / TPB;

    fused_decoder_kernel<<<blocks, TPB>>>(
        (const float4*)x, w1, g1, b1, w2, g2, b2, w3, b3, Bp,
        (float*)d_out, N);
}

// round 2
// speedup vs baseline: 1.4144x; 1.4144x over previous
#include <cuda_runtime.h>

typedef unsigned long long u64;

// ---- packed f32x2 helpers (FFMA2 path: only reachable via PTX fma.rn.f32x2) ----
__device__ __forceinline__ u64 pk2(float lo, float hi) {
    u64 r; asm("mov.b64 %0,{%1,%2};" : "=l"(r) : "f"(lo), "f"(hi)); return r;
}
__device__ __forceinline__ float2 upk2(u64 v) {
    float2 f; asm("mov.b64 {%0,%1},%2;" : "=f"(f.x), "=f"(f.y) : "l"(v)); return f;
}
__device__ __forceinline__ u64 fma2(u64 a, u64 b, u64 c) {
    u64 d; asm("fma.rn.f32x2 %0,%1,%2,%3;" : "=l"(d) : "l"(a), "l"(b), "l"(c)); return d;
}
__device__ __forceinline__ u64 add2(u64 a, u64 b) {
    u64 d; asm("add.rn.f32x2 %0,%1,%2;" : "=l"(d) : "l"(a), "l"(b)); return d;
}

#define TPB 128

// Thread pair (2t, 2t+1) owns rows (2p, 2p+1). Split-K: even lane accumulates
// even 16B x-chunks, odd lane odd chunks -> adjacent lanes read adjacent 16B
// (32B-contiguous, full sector use, 16 L1 wavefronts per warp LDG instead of 32).
// Partial sums exchanged via one shfl_xor pass; each lane then runs the full
// epilogue (LN1->ReLU->L2->LN2->ReLU->L3->normalize) for ONE row.
__global__ __launch_bounds__(TPB, 4)
void fused_decoder_kernel(const float4* __restrict__ x4,
                          const float*  __restrict__ w1,
                          const float*  __restrict__ g1,
                          const float*  __restrict__ b1,
                          const float*  __restrict__ w2,
                          const float*  __restrict__ g2,
                          const float*  __restrict__ b2,
                          const float*  __restrict__ w3,
                          const float*  __restrict__ b3,
                          const int*    __restrict__ Bp,
                          float*        __restrict__ out,
                          int N)
{
    // ---- stage all weights in shared memory ----
    __shared__ __align__(16) float sw1[64 * 32];   // 8 KB, row-major [k][j]
    __shared__ __align__(16) float sw2[32 * 16];   // 2 KB, row-major [k][j]
    __shared__ __align__(16) float sw3[48];
    __shared__ __align__(8)  float sg1[32], sb1[32], sg2[16], sb2[16];
    __shared__ float sb3v[3];

    const int tid = threadIdx.x;
    {
        const float4* w1v = (const float4*)w1;
        float4*       s1v = (float4*)sw1;
        #pragma unroll
        for (int i = 0; i < 4; i++) s1v[tid + i * TPB] = w1v[tid + i * TPB];
        const float4* w2v = (const float4*)w2;
        float4*       s2v = (float4*)sw2;
        s2v[tid & 127] = w2v[tid & 127];
        if (tid < 48) sw3[tid] = w3[tid];
        if (tid < 32) { sg1[tid] = g1[tid]; sb1[tid] = b1[tid]; }
        if (tid < 16) { sg2[tid] = g2[tid]; sb2[tid] = b2[tid]; }
        if (tid < 3)  sb3v[tid] = b3[tid];
    }
    __syncthreads();

    const ulonglong2* __restrict__ w1q = (const ulonglong2*)sw1; // 8 per k-row
    const ulonglong2* __restrict__ w2q = (const ulonglong2*)sw2; // 4 per k-row

    const int t = blockIdx.x * TPB + tid;
    const int e = t & 1;
    int r0 = t & ~1;
    if (r0 > N - 2) r0 = N - 2;          // clamp tail (N is even); store guarded below

    const int Bv = __ldg(Bp);
    const int HW = N / Bv;

    // ---- layer 1 (split-K over the pair): acc0 <- row r0, acc1 <- row r0+1 ----
    u64 acc0[16], acc1[16];
    #pragma unroll
    for (int jp = 0; jp < 16; jp++) { acc0[jp] = 0ull; acc1[jp] = 0ull; }

    const float4* __restrict__ px0 = x4 + (long)r0 * 16 + e;        // chunks e, e+2, ...
    const float4* __restrict__ px1 = x4 + (long)(r0 + 1) * 16 + e;

    float4 xa = px0[0];
    float4 xb = px1[0];

    #pragma unroll 1
    for (int kc = 0; kc < 8; kc++) {
        float4 na, nb;
        if (kc < 7) { na = px0[(kc + 1) * 2]; nb = px1[(kc + 1) * 2]; }
        else        { na = make_float4(0.f,0.f,0.f,0.f); nb = na; }

        const ulonglong2* __restrict__ wbase = w1q + ((kc * 2 + e) * 4) * 8;

        const float av[4] = {xa.x, xa.y, xa.z, xa.w};
        const float bv[4] = {xb.x, xb.y, xb.z, xb.w};
        #pragma unroll
        for (int q = 0; q < 4; q++) {
            const u64 da = pk2(av[q], av[q]);
            const u64 db = pk2(bv[q], bv[q]);
            const ulonglong2* __restrict__ wr = wbase + q * 8;
            #pragma unroll
            for (int j = 0; j < 8; j++) {
                const ulonglong2 w = wr[j];      // LDS.128: 4 output cols
                acc0[2*j]   = fma2(da, w.x, acc0[2*j]);
                acc0[2*j+1] = fma2(da, w.y, acc0[2*j+1]);
                acc1[2*j]   = fma2(db, w.x, acc1[2*j]);
                acc1[2*j+1] = fma2(db, w.y, acc1[2*j+1]);
            }
        }
        xa = na; xb = nb;
    }

    // ---- pair combine: full[] = my row's partial + partner's partial for my row ----
    // my epilogue row = r0 + e. I keep accE (E=e), I send acc(1-e) to partner.
    u64 full[16];
    #pragma unroll
    for (int jp = 0; jp < 16; jp++) {
        const u64 send = e ? acc0[jp] : acc1[jp];
        const u64 recv = __shfl_xor_sync(0xffffffffu, send, 1);
        const u64 mine = e ? acc1[jp] : acc0[jp];
        full[jp] = add2(mine, recv);
    }

    // ---- LayerNorm over 32 (tree reductions) ----
    {
        u64 s[8], q4[4];
        #pragma unroll
        for (int i = 0; i < 8; i++) s[i] = add2(full[i], full[i + 8]);
        #pragma unroll
        for (int i = 0; i < 4; i++) s[i] = add2(s[i], s[i + 4]);
        s[0] = add2(s[0], s[2]); s[1] = add2(s[1], s[3]);
        s[0] = add2(s[0], s[1]);
        float2 sf = upk2(s[0]);
        const float mean = (sf.x + sf.y) * (1.0f / 32.0f);

        #pragma unroll
        for (int i = 0; i < 4; i++) q4[i] = 0ull;
        #pragma unroll
        for (int jp = 0; jp < 16; jp++) q4[jp & 3] = fma2(full[jp], full[jp], q4[jp & 3]);
        q4[0] = add2(q4[0], q4[2]); q4[1] = add2(q4[1], q4[3]);
        q4[0] = add2(q4[0], q4[1]);
        float2 qf = upk2(q4[0]);
        const float var = (qf.x + qf.y) * (1.0f / 32.0f) - mean * mean;
        const float sc  = rsqrtf(var + 1e-5f);
        const float nms = -mean * sc;

        const u64 scp  = pk2(sc, sc);
        const u64 nmsp = pk2(nms, nms);
        const u64* __restrict__ g1p = (const u64*)sg1;
        const u64* __restrict__ b1p = (const u64*)sb1;

        float h1[32];
        #pragma unroll
        for (int jp = 0; jp < 16; jp++) {
            u64 vn = fma2(full[jp], scp, nmsp);
            vn = fma2(vn, g1p[jp], b1p[jp]);
            float2 vf = upk2(vn);
            h1[2*jp]   = fmaxf(vf.x, 0.0f);
            h1[2*jp+1] = fmaxf(vf.y, 0.0f);
        }

        // ---- layer 2: 32 -> 16 ----
        u64 a2[8];
        #pragma unroll
        for (int jp = 0; jp < 8; jp++) a2[jp] = 0ull;
        #pragma unroll
        for (int k2 = 0; k2 < 32; k2++) {
            const u64 hd = pk2(h1[k2], h1[k2]);
            const ulonglong2* __restrict__ wr = w2q + k2 * 4;
            #pragma unroll
            for (int j = 0; j < 4; j++) {
                const ulonglong2 w = wr[j];
                a2[2*j]   = fma2(hd, w.x, a2[2*j]);
                a2[2*j+1] = fma2(hd, w.y, a2[2*j+1]);
            }
        }

        // ---- LayerNorm over 16 ----
        u64 s2[4];
        #pragma unroll
        for (int i = 0; i < 4; i++) s2[i] = add2(a2[i], a2[i + 4]);
        s2[0] = add2(s2[0], s2[2]); s2[1] = add2(s2[1], s2[3]);
        s2[0] = add2(s2[0], s2[1]);
        float2 s2f = upk2(s2[0]);
        const float mean2 = (s2f.x + s2f.y) * (1.0f / 16.0f);

        u64 q2[2] = {0ull, 0ull};
        #pragma unroll
        for (int jp = 0; jp < 8; jp++) q2[jp & 1] = fma2(a2[jp], a2[jp], q2[jp & 1]);
        q2[0] = add2(q2[0], q2[1]);
        float2 q2f = upk2(q2[0]);
        const float var2 = (q2f.x + q2f.y) * (1.0f / 16.0f) - mean2 * mean2;
        const float sc2  = rsqrtf(var2 + 1e-5f);
        const float nms2 = -mean2 * sc2;

        const u64 sc2p  = pk2(sc2, sc2);
        const u64 nms2p = pk2(nms2, nms2);
        const u64* __restrict__ g2p = (const u64*)sg2;
        const u64* __restrict__ b2p = (const u64*)sb2;

        float h2[16];
        #pragma unroll
        for (int jp = 0; jp < 8; jp++) {
            u64 vn = fma2(a2[jp], sc2p, nms2p);
            vn = fma2(vn, g2p[jp], b2p[jp]);
            float2 vf = upk2(vn);
            h2[2*jp]   = fmaxf(vf.x, 0.0f);
            h2[2*jp+1] = fmaxf(vf.y, 0.0f);
        }

        // ---- layer 3: 16 -> 3 (+bias) ----
        float o0 = sb3v[0], o1 = sb3v[1], o2 = sb3v[2];
        #pragma unroll
        for (int k3 = 0; k3 < 16; k3++) {
            const float h = h2[k3];
            o0 = fmaf(h, sw3[k3 * 3 + 0], o0);
            o1 = fmaf(h, sw3[k3 * 3 + 1], o1);
            o2 = fmaf(h, sw3[k3 * 3 + 2], o2);
        }

        // ---- F.normalize along channel dim ----
        const float nn  = sqrtf(o0 * o0 + o1 * o1 + o2 * o2);
        const float inv = 1.0f / fmaxf(nn, 1e-12f);

        if (t < N) {
            const int row = r0 + e;
            const int b   = row / HW;
            const int hw  = row - b * HW;
            const int ob  = (b * 3) * HW + hw;
            out[ob]          = o0 * inv;
            out[ob + HW]     = o1 * inv;
            out[ob + 2*HW]   = o2 * inv;
        }
    }
}

extern "C" void kernel_launch(void* const* d_in, const int* in_sizes, int n_in,
                              void* d_out, int out_size)
{
    const float* x  = (const float*)d_in[0];
    const float* w1 = (const float*)d_in[1];
    const float* g1 = (const float*)d_in[2];
    const float* b1 = (const float*)d_in[3];
    const float* w2 = (const float*)d_in[4];
    const float* g2 = (const float*)d_in[5];
    const float* b2 = (const float*)d_in[6];
    const float* w3 = (const float*)d_in[7];
    const float* b3 = (const float*)d_in[8];
    const int*   Bp = (const int*)d_in[9];

    const int N = in_sizes[0] / 64;        // rows (one thread per row)
    const int blocks = (N + TPB - 1) / TPB;

    fused_decoder_kernel<<<blocks, TPB>>>(
        (const float4*)x, w1, g1, b1, w2, g2, b2, w3, b3, Bp,
        (float*)d_out, N);
}

// round 3
// speedup vs baseline: 1.7929x; 1.2676x over previous
#include <cuda_runtime.h>

typedef unsigned long long u64;

// ---- packed f32x2 helpers (FFMA2 path: only reachable via PTX fma.rn.f32x2) ----
__device__ __forceinline__ u64 pk2(float lo, float hi) {
    u64 r; asm("mov.b64 %0,{%1,%2};" : "=l"(r) : "f"(lo), "f"(hi)); return r;
}
__device__ __forceinline__ float2 upk2(u64 v) {
    float2 f; asm("mov.b64 {%0,%1},%2;" : "=f"(f.x), "=f"(f.y) : "l"(v)); return f;
}
__device__ __forceinline__ u64 fma2(u64 a, u64 b, u64 c) {
    u64 d; asm("fma.rn.f32x2 %0,%1,%2,%3;" : "=l"(d) : "l"(a), "l"(b), "l"(c)); return d;
}
__device__ __forceinline__ u64 add2(u64 a, u64 b) {
    u64 d; asm("add.rn.f32x2 %0,%1,%2;" : "=l"(d) : "l"(a), "l"(b)); return d;
}

#define TPB 128

// w1 smem layout: rows grouped by chunk parity p = (k>>2)&1.
//   parity-0 rows at float offset 0, parity-1 rows at offset 1024+16.
// The +16-float (64B) skew makes even-lane and odd-lane LDS.128 addresses land
// on DISJOINT bank groups (banks 4j..4j+3 vs 4j+16..4j+19) -> conflict-free
// 2-address broadcast instead of the 2-way conflict of the 128B-apart layout.
#define W1_ODD_OFF (1024 + 16)

__global__ __launch_bounds__(TPB, 4)
void fused_decoder_kernel(const float4* __restrict__ x4,
                          const float*  __restrict__ w1,
                          const float*  __restrict__ g1,
                          const float*  __restrict__ b1,
                          const float*  __restrict__ w2,
                          const float*  __restrict__ g2,
                          const float*  __restrict__ b2,
                          const float*  __restrict__ w3,
                          const float*  __restrict__ b3,
                          const int*    __restrict__ Bp,
                          float*        __restrict__ out,
                          int N)
{
    __shared__ __align__(16) float sw1s[W1_ODD_OFF + 1024];  // parity-split + skew
    __shared__ __align__(16) float sw2[32 * 16];
    __shared__ __align__(16) float sw3[48];
    __shared__ __align__(8)  float sg1[32], sb1[32], sg2[16], sb2[16];
    __shared__ float sb3v[3];

    const int tid = threadIdx.x;
    {
        // stage w1 with parity-split layout
        #pragma unroll
        for (int i = tid; i < 2048; i += TPB) {
            const int k = i >> 5, j = i & 31;
            const int p = (k >> 2) & 1;                 // chunk parity
            const int m = ((k >> 3) << 2) + (k & 3);    // row index within parity
            sw1s[(p ? W1_ODD_OFF : 0) + m * 32 + j] = w1[i];
        }
        const float4* w2v = (const float4*)w2;
        float4*       s2v = (float4*)sw2;
        s2v[tid & 127] = w2v[tid & 127];
        if (tid < 48) sw3[tid] = w3[tid];
        if (tid < 32) { sg1[tid] = g1[tid]; sb1[tid] = b1[tid]; }
        if (tid < 16) { sg2[tid] = g2[tid]; sb2[tid] = b2[tid]; }
        if (tid < 3)  sb3v[tid] = b3[tid];
    }
    __syncthreads();

    const ulonglong2* __restrict__ w2q = (const ulonglong2*)sw2; // 4 per k-row

    const int t = blockIdx.x * TPB + tid;
    const int e = t & 1;
    int r0 = t & ~1;
    if (r0 > N - 2) r0 = N - 2;          // clamp tail (N is even); store guarded below

    const int Bv = __ldg(Bp);
    const int HW = N / Bv;

    // per-parity weight base for this lane (conflict-free vs partner lane)
    const ulonglong2* __restrict__ w1k =
        (const ulonglong2*)(sw1s + (e ? W1_ODD_OFF : 0));

    // ---- layer 1 (split-K over the pair): acc0 <- row r0, acc1 <- row r0+1 ----
    u64 acc0[16], acc1[16];
    #pragma unroll
    for (int jp = 0; jp < 16; jp++) { acc0[jp] = 0ull; acc1[jp] = 0ull; }

    const float4* __restrict__ px0 = x4 + (long)r0 * 16 + e;        // chunks e, e+2, ...
    const float4* __restrict__ px1 = x4 + (long)(r0 + 1) * 16 + e;

    float4 xa = px0[0];
    float4 xb = px1[0];

    #pragma unroll 1
    for (int kc = 0; kc < 8; kc++) {
        float4 na, nb;
        if (kc < 7) { na = px0[(kc + 1) * 2]; nb = px1[(kc + 1) * 2]; }
        else        { na = make_float4(0.f,0.f,0.f,0.f); nb = na; }

        const float av[4] = {xa.x, xa.y, xa.z, xa.w};
        const float bv[4] = {xb.x, xb.y, xb.z, xb.w};
        #pragma unroll
        for (int q = 0; q < 4; q++) {
            const u64 da = pk2(av[q], av[q]);
            const u64 db = pk2(bv[q], bv[q]);
            // row m = kc*4+q within this lane's parity; 8 ulonglong2 per row
            const ulonglong2* __restrict__ wr = w1k + (kc * 4 + q) * 8;
            #pragma unroll
            for (int j = 0; j < 8; j++) {
                const ulonglong2 w = wr[j];      // LDS.128, bank-disjoint across the pair
                acc0[2*j]   = fma2(da, w.x, acc0[2*j]);
                acc0[2*j+1] = fma2(da, w.y, acc0[2*j+1]);
                acc1[2*j]   = fma2(db, w.x, acc1[2*j]);
                acc1[2*j+1] = fma2(db, w.y, acc1[2*j+1]);
            }
        }
        xa = na; xb = nb;
    }

    // ---- pair combine: full[] = my row's partial + partner's partial for my row ----
    u64 full[16];
    #pragma unroll
    for (int jp = 0; jp < 16; jp++) {
        const u64 send = e ? acc0[jp] : acc1[jp];
        const u64 recv = __shfl_xor_sync(0xffffffffu, send, 1);
        const u64 mine = e ? acc1[jp] : acc0[jp];
        full[jp] = add2(mine, recv);
    }

    // ---- LayerNorm over 32 (tree reductions) ----
    {
        u64 s[8], q4[4];
        #pragma unroll
        for (int i = 0; i < 8; i++) s[i] = add2(full[i], full[i + 8]);
        #pragma unroll
        for (int i = 0; i < 4; i++) s[i] = add2(s[i], s[i + 4]);
        s[0] = add2(s[0], s[2]); s[1] = add2(s[1], s[3]);
        s[0] = add2(s[0], s[1]);
        float2 sf = upk2(s[0]);
        const float mean = (sf.x + sf.y) * (1.0f / 32.0f);

        #pragma unroll
        for (int i = 0; i < 4; i++) q4[i] = 0ull;
        #pragma unroll
        for (int jp = 0; jp < 16; jp++) q4[jp & 3] = fma2(full[jp], full[jp], q4[jp & 3]);
        q4[0] = add2(q4[0], q4[2]); q4[1] = add2(q4[1], q4[3]);
        q4[0] = add2(q4[0], q4[1]);
        float2 qf = upk2(q4[0]);
        const float var = (qf.x + qf.y) * (1.0f / 32.0f) - mean * mean;
        const float sc  = rsqrtf(var + 1e-5f);
        const float nms = -mean * sc;

        const u64 scp  = pk2(sc, sc);
        const u64 nmsp = pk2(nms, nms);
        const u64* __restrict__ g1p = (const u64*)sg1;
        const u64* __restrict__ b1p = (const u64*)sb1;

        float h1[32];
        #pragma unroll
        for (int jp = 0; jp < 16; jp++) {
            u64 vn = fma2(full[jp], scp, nmsp);
            vn = fma2(vn, g1p[jp], b1p[jp]);
            float2 vf = upk2(vn);
            h1[2*jp]   = fmaxf(vf.x, 0.0f);
            h1[2*jp+1] = fmaxf(vf.y, 0.0f);
        }

        // ---- layer 2: 32 -> 16 ----
        u64 a2[8];
        #pragma unroll
        for (int jp = 0; jp < 8; jp++) a2[jp] = 0ull;
        #pragma unroll
        for (int k2 = 0; k2 < 32; k2++) {
            const u64 hd = pk2(h1[k2], h1[k2]);
            const ulonglong2* __restrict__ wr = w2q + k2 * 4;
            #pragma unroll
            for (int j = 0; j < 4; j++) {
                const ulonglong2 w = wr[j];      // warp-uniform broadcast
                a2[2*j]   = fma2(hd, w.x, a2[2*j]);
                a2[2*j+1] = fma2(hd, w.y, a2[2*j+1]);
            }
        }

        // ---- LayerNorm over 16 ----
        u64 s2[4];
        #pragma unroll
        for (int i = 0; i < 4; i++) s2[i] = add2(a2[i], a2[i + 4]);
        s2[0] = add2(s2[0], s2[2]); s2[1] = add2(s2[1], s2[3]);
        s2[0] = add2(s2[0], s2[1]);
        float2 s2f = upk2(s2[0]);
        const float mean2 = (s2f.x + s2f.y) * (1.0f / 16.0f);

        u64 q2[2] = {0ull, 0ull};
        #pragma unroll
        for (int jp = 0; jp < 8; jp++) q2[jp & 1] = fma2(a2[jp], a2[jp], q2[jp & 1]);
        q2[0] = add2(q2[0], q2[1]);
        float2 q2f = upk2(q2[0]);
        const float var2 = (q2f.x + q2f.y) * (1.0f / 16.0f) - mean2 * mean2;
        const float sc2  = rsqrtf(var2 + 1e-5f);
        const float nms2 = -mean2 * sc2;

        const u64 sc2p  = pk2(sc2, sc2);
        const u64 nms2p = pk2(nms2, nms2);
        const u64* __restrict__ g2p = (const u64*)sg2;
        const u64* __restrict__ b2p = (const u64*)sb2;

        float h2[16];
        #pragma unroll
        for (int jp = 0; jp < 8; jp++) {
            u64 vn = fma2(a2[jp], sc2p, nms2p);
            vn = fma2(vn, g2p[jp], b2p[jp]);
            float2 vf = upk2(vn);
            h2[2*jp]   = fmaxf(vf.x, 0.0f);
            h2[2*jp+1] = fmaxf(vf.y, 0.0f);
        }

        // ---- layer 3: 16 -> 3 (+bias) ----
        float o0 = sb3v[0], o1 = sb3v[1], o2 = sb3v[2];
        #pragma unroll
        for (int k3 = 0; k3 < 16; k3++) {
            const float h = h2[k3];
            o0 = fmaf(h, sw3[k3 * 3 + 0], o0);
            o1 = fmaf(h, sw3[k3 * 3 + 1], o1);
            o2 = fmaf(h, sw3[k3 * 3 + 2], o2);
        }

        // ---- F.normalize along channel dim ----
        const float nn  = sqrtf(o0 * o0 + o1 * o1 + o2 * o2);
        const float inv = 1.0f / fmaxf(nn, 1e-12f);

        if (t < N) {
            const int row = r0 + e;
            const int b   = row / HW;
            const int hw  = row - b * HW;
            const int ob  = (b * 3) * HW + hw;
            out[ob]          = o0 * inv;
            out[ob + HW]     = o1 * inv;
            out[ob + 2*HW]   = o2 * inv;
        }
    }
}

extern "C" void kernel_launch(void* const* d_in, const int* in_sizes, int n_in,
                              void* d_out, int out_size)
{
    const float* x  = (const float*)d_in[0];
    const float* w1 = (const float*)d_in[1];
    const float* g1 = (const float*)d_in[2];
    const float* b1 = (const float*)d_in[3];
    const float* w2 = (const float*)d_in[4];
    const float* g2 = (const float*)d_in[5];
    const float* b2 = (const float*)d_in[6];
    const float* w3 = (const float*)d_in[7];
    const float* b3 = (const float*)d_in[8];
    const int*   Bp = (const int*)d_in[9];

    const int N = in_sizes[0] / 64;        // rows (one thread per row)
    const int blocks = (N + TPB - 1) / TPB;

    fused_decoder_kernel<<<blocks, TPB>>>(
        (const float4*)x, w1, g1, b1, w2, g2, b2, w3, b3, Bp,
        (float*)d_out, N);
}

// round 5
// speedup vs baseline: 2.4537x; 1.3686x over previous
#include <cuda_runtime.h>
#include <cuda_bf16.h>

typedef unsigned long long u64;
typedef unsigned int u32;

// ---------------- packed f32x2 helpers ----------------
__device__ __forceinline__ u64 pk2(float lo, float hi) {
    u64 r; asm("mov.b64 %0,{%1,%2};" : "=l"(r) : "f"(lo), "f"(hi)); return r;
}
__device__ __forceinline__ float2 upk2(u64 v) {
    float2 f; asm("mov.b64 {%0,%1},%2;" : "=f"(f.x), "=f"(f.y) : "l"(v)); return f;
}
__device__ __forceinline__ u64 fma2(u64 a, u64 b, u64 c) {
    u64 d; asm("fma.rn.f32x2 %0,%1,%2,%3;" : "=l"(d) : "l"(a), "l"(b), "l"(c)); return d;
}
__device__ __forceinline__ u64 add2(u64 a, u64 b) {
    u64 d; asm("add.rn.f32x2 %0,%1,%2;" : "=l"(d) : "l"(a), "l"(b)); return d;
}

// ---------------- HMMA: m16n8k16 row.col f32.bf16.bf16.f32 (sm_80 baseline) ----------------
__device__ __forceinline__ void mma_bf16(float& d0, float& d1, float& d2, float& d3,
                                         u32 a0, u32 a1, u32 a2, u32 a3,
                                         u32 b0, u32 b1) {
    asm volatile(
        "mma.sync.aligned.m16n8k16.row.col.f32.bf16.bf16.f32 "
        "{%0,%1,%2,%3}, {%4,%5,%6,%7}, {%8,%9}, {%0,%1,%2,%3};"
        : "+f"(d0), "+f"(d1), "+f"(d2), "+f"(d3)
        : "r"(a0), "r"(a1), "r"(a2), "r"(a3), "r"(b0), "r"(b1));
}

// float2 -> bf16x2 hi + bf16x2 lo (residual), element 0 in low half
__device__ __forceinline__ void cvt_hilo(float2 p, u32& hi, u32& lo) {
    __nv_bfloat162 h = __float22bfloat162_rn(p);
    hi = *reinterpret_cast<u32*>(&h);
    float2 res = make_float2(p.x - __bfloat162float(h.x),
                             p.y - __bfloat162float(h.y));
    __nv_bfloat162 l = __float22bfloat162_rn(res);
    lo = *reinterpret_cast<u32*>(&l);
}

#define TPB    128
#define NCTAS  592      // 148 SM * 4
#define PITCH  33       // D-buffer row pitch (floats): conflict-free row gather

__global__ __launch_bounds__(TPB, 4)
void fused_decoder_hmma(const float* __restrict__ x,
                        const float* __restrict__ w1,
                        const float* __restrict__ g1,
                        const float* __restrict__ b1,
                        const float* __restrict__ w2,
                        const float* __restrict__ g2,
                        const float* __restrict__ b2,
                        const float* __restrict__ w3,
                        const float* __restrict__ b3,
                        const int*   __restrict__ Bp,
                        float*       __restrict__ out,
                        int N, int ngroups)
{
    // D scratch: one 32x32 fp32 tile per warp, pitch 33 (conflict-free LDS.32 rows)
    __shared__ float sD[4][32 * PITCH];                 // 16896 B
    // B fragments (bf16 hi/lo) in exact mma layout: [kb*4+nb][lane] = {b0,b1}
    __shared__ __align__(16) uint2 sBH[16][32];         // 4 KB
    __shared__ __align__(16) uint2 sBL[16][32];         // 4 KB
    __shared__ __align__(16) float sw2[32 * 16];
    __shared__ __align__(16) float sw3[48];
    __shared__ __align__(8)  float sg1[32], sb1[32], sg2[16], sb2[16];
    __shared__ float sb3v[3];

    const int tid  = threadIdx.x;
    const int wid  = tid >> 5;
    const int lane = tid & 31;

    // ---- one-time staging: B fragments for w1 (hi + lo), plus tail weights ----
    for (int e = tid; e < 512; e += TPB) {
        const int kn = e >> 5, l = e & 31;
        const int kb = kn >> 2, nb = kn & 3;
        const int c  = (l & 3) * 2;        // k offset within k16 block
        const int g  = l >> 2;             // n offset within n8 block
        const int col  = nb * 8 + g;
        const int krow = kb * 16 + c;
        const float f0 = w1[(krow + 0) * 32 + col];
        const float f1 = w1[(krow + 1) * 32 + col];
        const float f2 = w1[(krow + 8) * 32 + col];
        const float f3 = w1[(krow + 9) * 32 + col];
        u32 h01, l01, h23, l23;
        cvt_hilo(make_float2(f0, f1), h01, l01);
        cvt_hilo(make_float2(f2, f3), h23, l23);
        sBH[kn][l] = make_uint2(h01, h23);
        sBL[kn][l] = make_uint2(l01, l23);
    }
    {
        const float4* w2v = (const float4*)w2;
        float4*       s2v = (float4*)sw2;
        s2v[tid & 127] = w2v[tid & 127];
        if (tid < 48) sw3[tid] = w3[tid];
        if (tid < 32) { sg1[tid] = g1[tid]; sb1[tid] = b1[tid]; }
        if (tid < 16) { sg2[tid] = g2[tid]; sb2[tid] = b2[tid]; }
        if (tid < 3)  sb3v[tid] = b3[tid];
    }
    __syncthreads();

    const int Bv = __ldg(Bp);
    const int HW = N / Bv;

    const ulonglong2* __restrict__ w2q = (const ulonglong2*)sw2;
    float* __restrict__ sDw = sD[wid];

    const int gw0    = blockIdx.x * 4 + wid;     // global warp id
    const int nwarps = gridDim.x * 4;

    const int g8 = lane >> 2;          // 0..7  (row within 8-row group)
    const int c2 = (lane & 3) * 2;     // 0,2,4,6 (col pair)

    #pragma unroll 1
    for (int grp = gw0; grp < ngroups; grp += nwarps) {
        const int R = grp * 32;

        // ---- layer 1 on HMMA: two 16-row m-blocks ----
        #pragma unroll
        for (int mb = 0; mb < 2; mb++) {
            int r0 = R + mb * 16 + g8;     if (r0 > N - 1) r0 = N - 1;
            int r1 = R + mb * 16 + g8 + 8; if (r1 > N - 1) r1 = N - 1;
            const float* xr0 = x + (size_t)r0 * 64 + c2;
            const float* xr1 = x + (size_t)r1 * 64 + c2;

            // A fragments: hi + lo, 4 k-blocks
            u32 ah[4][4], al[4][4];
            #pragma unroll
            for (int kb = 0; kb < 4; kb++) {
                const float2 p0 = *(const float2*)(xr0 + kb * 16);
                const float2 p1 = *(const float2*)(xr1 + kb * 16);
                const float2 p2 = *(const float2*)(xr0 + kb * 16 + 8);
                const float2 p3 = *(const float2*)(xr1 + kb * 16 + 8);
                cvt_hilo(p0, ah[kb][0], al[kb][0]);
                cvt_hilo(p1, ah[kb][1], al[kb][1]);
                cvt_hilo(p2, ah[kb][2], al[kb][2]);
                cvt_hilo(p3, ah[kb][3], al[kb][3]);
            }

            #pragma unroll
            for (int nb = 0; nb < 4; nb++) {
                float d0 = 0.f, d1 = 0.f, d2 = 0.f, d3 = 0.f;
                #pragma unroll
                for (int kb = 0; kb < 4; kb++) {
                    const uint2 bh = sBH[kb * 4 + nb][lane];   // LDS.64, conflict-free
                    const uint2 bl = sBL[kb * 4 + nb][lane];
                    mma_bf16(d0,d1,d2,d3, ah[kb][0],ah[kb][1],ah[kb][2],ah[kb][3], bh.x, bh.y);
                    mma_bf16(d0,d1,d2,d3, ah[kb][0],ah[kb][1],ah[kb][2],ah[kb][3], bl.x, bl.y);
                    mma_bf16(d0,d1,d2,d3, al[kb][0],al[kb][1],al[kb][2],al[kb][3], bh.x, bh.y);
                }
                // scatter D frag to scratch (scalar STS: pitch 33 keeps 4B align)
                float* dr0 = sDw + (mb * 16 + g8)     * PITCH + nb * 8 + c2;
                float* dr1 = sDw + (mb * 16 + g8 + 8) * PITCH + nb * 8 + c2;
                dr0[0] = d0; dr0[1] = d1;
                dr1[0] = d2; dr1[1] = d3;
            }
        }
        __syncwarp();

        // ---- lane gathers its row (conflict-free: (33*lane + c) % 32 distinct) ----
        u64 full[16];
        {
            const float* rowp = sDw + lane * PITCH;
            #pragma unroll
            for (int jp = 0; jp < 16; jp++)
                full[jp] = pk2(rowp[2 * jp], rowp[2 * jp + 1]);
        }

        // ---- LayerNorm over 32 ----
        u64 s[8], q4[4];
        #pragma unroll
        for (int i = 0; i < 8; i++) s[i] = add2(full[i], full[i + 8]);
        #pragma unroll
        for (int i = 0; i < 4; i++) s[i] = add2(s[i], s[i + 4]);
        s[0] = add2(s[0], s[2]); s[1] = add2(s[1], s[3]);
        s[0] = add2(s[0], s[1]);
        float2 sf = upk2(s[0]);
        const float mean = (sf.x + sf.y) * (1.0f / 32.0f);

        #pragma unroll
        for (int i = 0; i < 4; i++) q4[i] = 0ull;
        #pragma unroll
        for (int jp = 0; jp < 16; jp++) q4[jp & 3] = fma2(full[jp], full[jp], q4[jp & 3]);
        q4[0] = add2(q4[0], q4[2]); q4[1] = add2(q4[1], q4[3]);
        q4[0] = add2(q4[0], q4[1]);
        float2 qf = upk2(q4[0]);
        const float var = (qf.x + qf.y) * (1.0f / 32.0f) - mean * mean;
        const float sc  = rsqrtf(var + 1e-5f);
        const float nms = -mean * sc;

        const u64 scp  = pk2(sc, sc);
        const u64 nmsp = pk2(nms, nms);
        const u64* __restrict__ g1p = (const u64*)sg1;
        const u64* __restrict__ b1p = (const u64*)sb1;

        float h1[32];
        #pragma unroll
        for (int jp = 0; jp < 16; jp++) {
            u64 vn = fma2(full[jp], scp, nmsp);
            vn = fma2(vn, g1p[jp], b1p[jp]);
            float2 vf = upk2(vn);
            h1[2*jp]   = fmaxf(vf.x, 0.0f);
            h1[2*jp+1] = fmaxf(vf.y, 0.0f);
        }

        // ---- layer 2: 32 -> 16 (packed fp32) ----
        u64 a2[8];
        #pragma unroll
        for (int jp = 0; jp < 8; jp++) a2[jp] = 0ull;
        #pragma unroll
        for (int k2 = 0; k2 < 32; k2++) {
            const u64 hd = pk2(h1[k2], h1[k2]);
            const ulonglong2* __restrict__ wr = w2q + k2 * 4;
            #pragma unroll
            for (int j = 0; j < 4; j++) {
                const ulonglong2 w = wr[j];      // warp-uniform broadcast
                a2[2*j]   = fma2(hd, w.x, a2[2*j]);
                a2[2*j+1] = fma2(hd, w.y, a2[2*j+1]);
            }
        }

        // ---- LayerNorm over 16 ----
        u64 s2[4];
        #pragma unroll
        for (int i = 0; i < 4; i++) s2[i] = add2(a2[i], a2[i + 4]);
        s2[0] = add2(s2[0], s2[2]); s2[1] = add2(s2[1], s2[3]);
        s2[0] = add2(s2[0], s2[1]);
        float2 s2f = upk2(s2[0]);
        const float mean2 = (s2f.x + s2f.y) * (1.0f / 16.0f);

        u64 q2[2] = {0ull, 0ull};
        #pragma unroll
        for (int jp = 0; jp < 8; jp++) q2[jp & 1] = fma2(a2[jp], a2[jp], q2[jp & 1]);
        q2[0] = add2(q2[0], q2[1]);
        float2 q2f = upk2(q2[0]);
        const float var2 = (q2f.x + q2f.y) * (1.0f / 16.0f) - mean2 * mean2;
        const float sc2  = rsqrtf(var2 + 1e-5f);
        const float nms2 = -mean2 * sc2;

        const u64 sc2p  = pk2(sc2, sc2);
        const u64 nms2p = pk2(nms2, nms2);
        const u64* __restrict__ g2p = (const u64*)sg2;
        const u64* __restrict__ b2p = (const u64*)sb2;

        float h2[16];
        #pragma unroll
        for (int jp = 0; jp < 8; jp++) {
            u64 vn = fma2(a2[jp], sc2p, nms2p);
            vn = fma2(vn, g2p[jp], b2p[jp]);
            float2 vf = upk2(vn);
            h2[2*jp]   = fmaxf(vf.x, 0.0f);
            h2[2*jp+1] = fmaxf(vf.y, 0.0f);
        }

        // ---- layer 3: 16 -> 3 (+bias) ----
        float o0 = sb3v[0], o1 = sb3v[1], o2 = sb3v[2];
        #pragma unroll
        for (int k3 = 0; k3 < 16; k3++) {
            const float h = h2[k3];
            o0 = fmaf(h, sw3[k3 * 3 + 0], o0);
            o1 = fmaf(h, sw3[k3 * 3 + 1], o1);
            o2 = fmaf(h, sw3[k3 * 3 + 2], o2);
        }

        // ---- F.normalize + scatter to [B, 3, H, W] ----
        const float nn  = sqrtf(o0 * o0 + o1 * o1 + o2 * o2);
        const float inv = 1.0f / fmaxf(nn, 1e-12f);

        const int row = R + lane;
        if (row < N) {
            const int b  = row / HW;
            const int hw = row - b * HW;
            const int ob = (b * 3) * HW + hw;
            out[ob]          = o0 * inv;
            out[ob + HW]     = o1 * inv;
            out[ob + 2*HW]   = o2 * inv;
        }
        __syncwarp();   // D scratch consumed before next iteration overwrites
    }
}

extern "C" void kernel_launch(void* const* d_in, const int* in_sizes, int n_in,
                              void* d_out, int out_size)
{
    const float* x  = (const float*)d_in[0];
    const float* w1 = (const float*)d_in[1];
    const float* g1 = (const float*)d_in[2];
    const float* b1 = (const float*)d_in[3];
    const float* w2 = (const float*)d_in[4];
    const float* g2 = (const float*)d_in[5];
    const float* b2 = (const float*)d_in[6];
    const float* w3 = (const float*)d_in[7];
    const float* b3 = (const float*)d_in[8];
    const int*   Bp = (const int*)d_in[9];

    const int N       = in_sizes[0] / 64;
    const int ngroups = (N + 31) / 32;
    int blocks = (ngroups + 3) / 4;
    if (blocks > NCTAS) blocks = NCTAS;

    fused_decoder_hmma<<<blocks, TPB>>>(
        x, w1, g1, b1, w2, g2, b2, w3, b3, Bp,
        (float*)d_out, N, ngroups);
}

// round 6
// speedup vs baseline: 3.1326x; 1.2767x over previous
#include <cuda_runtime.h>
#include <cuda_bf16.h>

typedef unsigned long long u64;
typedef unsigned int u32;

// ---------------- packed f32x2 helpers ----------------
__device__ __forceinline__ u64 pk2(float lo, float hi) {
    u64 r; asm("mov.b64 %0,{%1,%2};" : "=l"(r) : "f"(lo), "f"(hi)); return r;
}
__device__ __forceinline__ float2 upk2(u64 v) {
    float2 f; asm("mov.b64 {%0,%1},%2;" : "=f"(f.x), "=f"(f.y) : "l"(v)); return f;
}
__device__ __forceinline__ u64 fma2(u64 a, u64 b, u64 c) {
    u64 d; asm("fma.rn.f32x2 %0,%1,%2,%3;" : "=l"(d) : "l"(a), "l"(b), "l"(c)); return d;
}
__device__ __forceinline__ u64 add2(u64 a, u64 b) {
    u64 d; asm("add.rn.f32x2 %0,%1,%2;" : "=l"(d) : "l"(a), "l"(b)); return d;
}

// ---------------- HMMA m16n8k16 row.col f32.bf16.bf16.f32 ----------------
__device__ __forceinline__ void mma_bf16(float& d0, float& d1, float& d2, float& d3,
                                         u32 a0, u32 a1, u32 a2, u32 a3,
                                         u32 b0, u32 b1) {
    asm volatile(
        "mma.sync.aligned.m16n8k16.row.col.f32.bf16.bf16.f32 "
        "{%0,%1,%2,%3}, {%4,%5,%6,%7}, {%8,%9}, {%0,%1,%2,%3};"
        : "+f"(d0), "+f"(d1), "+f"(d2), "+f"(d3)
        : "r"(a0), "r"(a1), "r"(a2), "r"(a3), "r"(b0), "r"(b1));
}

// two floats -> bf16x2 hi (v0 low half, v1 high half) + bf16x2 residual lo
__device__ __forceinline__ void split2(float v0, float v1, u32& h, u32& l) {
    __nv_bfloat162 hb = __float22bfloat162_rn(make_float2(v0, v1));
    h = *reinterpret_cast<u32*>(&hb);
    float r0 = v0 - __bfloat162float(hb.x);
    float r1 = v1 - __bfloat162float(hb.y);
    __nv_bfloat162 lb = __float22bfloat162_rn(make_float2(r0, r1));
    l = *reinterpret_cast<u32*>(&lb);
}

__device__ __forceinline__ u64 shflx(u64 v, int m) {
    return (u64)__shfl_xor_sync(0xffffffffu, (unsigned long long)v, m);
}

#define TPB    128
#define NCTAS  592

__global__ __launch_bounds__(TPB, 4)
void fused_decoder_frag(const float* __restrict__ x,
                        const float* __restrict__ w1,
                        const float* __restrict__ g1v,
                        const float* __restrict__ b1v,
                        const float* __restrict__ w2,
                        const float* __restrict__ g2v,
                        const float* __restrict__ b2v,
                        const float* __restrict__ w3,
                        const float* __restrict__ b3,
                        const int*   __restrict__ Bp,
                        float*       __restrict__ out,
                        int N, int ngroups)
{
    // w1 B-fragments (bf16 hi/lo), mma layout: [kb*4+nb][lane] = {b0,b1}
    __shared__ __align__(16) uint2 sBH[16][32];
    __shared__ __align__(16) uint2 sBL[16][32];

    const int tid  = threadIdx.x;
    const int wid  = tid >> 5;
    const int lane = tid & 31;
    const int g    = lane >> 2;        // row-in-group 0..7
    const int t    = lane & 3;         // col-pair selector

    // ---- one-time: stage w1 B-frags (identical to validated round-5 code) ----
    for (int e = tid; e < 512; e += TPB) {
        const int kn = e >> 5, l = e & 31;
        const int kb = kn >> 2, nb = kn & 3;
        const int c  = (l & 3) * 2;
        const int gg = l >> 2;
        const int col  = nb * 8 + gg;
        const int krow = kb * 16 + c;
        u32 h01, l01, h23, l23;
        split2(w1[(krow + 0) * 32 + col], w1[(krow + 1) * 32 + col], h01, l01);
        split2(w1[(krow + 8) * 32 + col], w1[(krow + 9) * 32 + col], h23, l23);
        sBH[kn][l] = make_uint2(h01, h23);
        sBL[kn][l] = make_uint2(l01, l23);
    }
    __syncthreads();

    // ---- per-lane register constants ----
    // w2 (32x16) B-frags: [kb2][nb2][0/1], hi+lo
    u32 w2h[2][2][2], w2l[2][2][2];
    #pragma unroll
    for (int kb2 = 0; kb2 < 2; kb2++)
        #pragma unroll
        for (int nb2 = 0; nb2 < 2; nb2++) {
            const int col = nb2 * 8 + g;
            const int k0  = kb2 * 16 + 2 * t;
            split2(w2[k0 * 16 + col],       w2[(k0 + 1) * 16 + col], w2h[kb2][nb2][0], w2l[kb2][nb2][0]);
            split2(w2[(k0 + 8) * 16 + col], w2[(k0 + 9) * 16 + col], w2h[kb2][nb2][1], w2l[kb2][nb2][1]);
        }
    // w3 (16x3, n-padded to 8) B-frags
    u32 w3h[2] = {0u, 0u}, w3l[2] = {0u, 0u};
    if (g < 3) {
        const int k0 = 2 * t;
        split2(w3[k0 * 3 + g],       w3[(k0 + 1) * 3 + g], w3h[0], w3l[0]);
        split2(w3[(k0 + 8) * 3 + g], w3[(k0 + 9) * 3 + g], w3h[1], w3l[1]);
    }
    // gamma/beta pairs for this lane's columns
    u64 g1p[4], b1p[4];
    #pragma unroll
    for (int nb = 0; nb < 4; nb++) {
        const int c0 = nb * 8 + 2 * t;
        g1p[nb] = pk2(g1v[c0], g1v[c0 + 1]);
        b1p[nb] = pk2(b1v[c0], b1v[c0 + 1]);
    }
    u64 g2p[2], b2p[2];
    #pragma unroll
    for (int nb2 = 0; nb2 < 2; nb2++) {
        const int c0 = nb2 * 8 + 2 * t;
        g2p[nb2] = pk2(g2v[c0], g2v[c0 + 1]);
        b2p[nb2] = pk2(b2v[c0], b2v[c0 + 1]);
    }
    const float bb0 = b3[0], bb1 = b3[1], bb2 = b3[2];

    const int Bv = __ldg(Bp);
    const int HW = N / Bv;

    const int gw0    = blockIdx.x * 4 + wid;
    const int nwarps = gridDim.x * 4;

    #pragma unroll 1
    for (int grp = gw0; grp < ngroups; grp += nwarps) {
        const int R = grp * 16;
        int r0 = R + g;     if (r0 > N - 1) r0 = N - 1;
        int r1 = R + g + 8; if (r1 > N - 1) r1 = N - 1;
        const float* xr0 = x + (size_t)r0 * 64 + 2 * t;
        const float* xr1 = x + (size_t)r1 * 64 + 2 * t;

        // ---- x A-frags (hi/lo) ----
        u32 ah[4][4], al[4][4];
        #pragma unroll
        for (int kb = 0; kb < 4; kb++) {
            const float2 p0 = *(const float2*)(xr0 + kb * 16);
            const float2 p1 = *(const float2*)(xr1 + kb * 16);
            const float2 p2 = *(const float2*)(xr0 + kb * 16 + 8);
            const float2 p3 = *(const float2*)(xr1 + kb * 16 + 8);
            split2(p0.x, p0.y, ah[kb][0], al[kb][0]);
            split2(p1.x, p1.y, ah[kb][1], al[kb][1]);
            split2(p2.x, p2.y, ah[kb][2], al[kb][2]);
            split2(p3.x, p3.y, ah[kb][3], al[kb][3]);
        }

        // ---- layer 1: 4 n-blocks on HMMA ----
        float d1[4][4];
        #pragma unroll
        for (int nb = 0; nb < 4; nb++) {
            float d0 = 0.f, dd1 = 0.f, d2 = 0.f, d3 = 0.f;
            #pragma unroll
            for (int kb = 0; kb < 4; kb++) {
                const uint2 bh = sBH[kb * 4 + nb][lane];
                const uint2 bl = sBL[kb * 4 + nb][lane];
                mma_bf16(d0,dd1,d2,d3, ah[kb][0],ah[kb][1],ah[kb][2],ah[kb][3], bh.x, bh.y);
                mma_bf16(d0,dd1,d2,d3, ah[kb][0],ah[kb][1],ah[kb][2],ah[kb][3], bl.x, bl.y);
                mma_bf16(d0,dd1,d2,d3, al[kb][0],al[kb][1],al[kb][2],al[kb][3], bh.x, bh.y);
            }
            d1[nb][0] = d0; d1[nb][1] = dd1; d1[nb][2] = d2; d1[nb][3] = d3;
        }

        // ---- LN1 in frag layout: quad shuffle stats, packed (row g, row g+8) ----
        u64 ss = 0ull, qq = 0ull;
        #pragma unroll
        for (int nb = 0; nb < 4; nb++) {
            const u64 m0 = pk2(d1[nb][0], d1[nb][2]);
            const u64 m1 = pk2(d1[nb][1], d1[nb][3]);
            ss = add2(ss, add2(m0, m1));
            qq = fma2(m0, m0, fma2(m1, m1, qq));
        }
        ss = add2(ss, shflx(ss, 1)); ss = add2(ss, shflx(ss, 2));
        qq = add2(qq, shflx(qq, 1)); qq = add2(qq, shflx(qq, 2));
        float2 sv = upk2(ss), qv = upk2(qq);
        const float mgA = sv.x * (1.0f/32.0f), mgB = sv.y * (1.0f/32.0f);
        const float scA = rsqrtf(qv.x * (1.0f/32.0f) - mgA * mgA + 1e-5f);
        const float scB = rsqrtf(qv.y * (1.0f/32.0f) - mgB * mgB + 1e-5f);
        const u64 scpA = pk2(scA, scA), nmpA = pk2(-mgA*scA, -mgA*scA);
        const u64 scpB = pk2(scB, scB), nmpB = pk2(-mgB*scB, -mgB*scB);

        u32 hh[4][2], hl[4][2];
        #pragma unroll
        for (int nb = 0; nb < 4; nb++) {
            u64 u0 = fma2(fma2(pk2(d1[nb][0], d1[nb][1]), scpA, nmpA), g1p[nb], b1p[nb]);
            u64 u1 = fma2(fma2(pk2(d1[nb][2], d1[nb][3]), scpB, nmpB), g1p[nb], b1p[nb]);
            float2 f0 = upk2(u0), f1 = upk2(u1);
            split2(fmaxf(f0.x, 0.f), fmaxf(f0.y, 0.f), hh[nb][0], hl[nb][0]);
            split2(fmaxf(f1.x, 0.f), fmaxf(f1.y, 0.f), hh[nb][1], hl[nb][1]);
        }

        // ---- layer 2 on HMMA (w2 frags in regs); D1-frag IS A2-frag ----
        float d2f[2][4];
        #pragma unroll
        for (int nb2 = 0; nb2 < 2; nb2++) {
            float d0 = 0.f, dd1 = 0.f, d2 = 0.f, d3 = 0.f;
            #pragma unroll
            for (int kb2 = 0; kb2 < 2; kb2++) {
                const int na = kb2 * 2;
                mma_bf16(d0,dd1,d2,d3, hh[na][0],hh[na][1],hh[na+1][0],hh[na+1][1],
                         w2h[kb2][nb2][0], w2h[kb2][nb2][1]);
                mma_bf16(d0,dd1,d2,d3, hh[na][0],hh[na][1],hh[na+1][0],hh[na+1][1],
                         w2l[kb2][nb2][0], w2l[kb2][nb2][1]);
                mma_bf16(d0,dd1,d2,d3, hl[na][0],hl[na][1],hl[na+1][0],hl[na+1][1],
                         w2h[kb2][nb2][0], w2h[kb2][nb2][1]);
            }
            d2f[nb2][0] = d0; d2f[nb2][1] = dd1; d2f[nb2][2] = d2; d2f[nb2][3] = d3;
        }

        // ---- LN2 ----
        u64 ss2 = 0ull, qq2 = 0ull;
        #pragma unroll
        for (int nb2 = 0; nb2 < 2; nb2++) {
            const u64 m0 = pk2(d2f[nb2][0], d2f[nb2][2]);
            const u64 m1 = pk2(d2f[nb2][1], d2f[nb2][3]);
            ss2 = add2(ss2, add2(m0, m1));
            qq2 = fma2(m0, m0, fma2(m1, m1, qq2));
        }
        ss2 = add2(ss2, shflx(ss2, 1)); ss2 = add2(ss2, shflx(ss2, 2));
        qq2 = add2(qq2, shflx(qq2, 1)); qq2 = add2(qq2, shflx(qq2, 2));
        float2 sv2 = upk2(ss2), qv2 = upk2(qq2);
        const float m2A = sv2.x * (1.0f/16.0f), m2B = sv2.y * (1.0f/16.0f);
        const float s2A = rsqrtf(qv2.x * (1.0f/16.0f) - m2A * m2A + 1e-5f);
        const float s2B = rsqrtf(qv2.y * (1.0f/16.0f) - m2B * m2B + 1e-5f);
        const u64 sc2pA = pk2(s2A, s2A), nm2pA = pk2(-m2A*s2A, -m2A*s2A);
        const u64 sc2pB = pk2(s2B, s2B), nm2pB = pk2(-m2B*s2B, -m2B*s2B);

        u32 h2h[2][2], h2l[2][2];
        #pragma unroll
        for (int nb2 = 0; nb2 < 2; nb2++) {
            u64 u0 = fma2(fma2(pk2(d2f[nb2][0], d2f[nb2][1]), sc2pA, nm2pA), g2p[nb2], b2p[nb2]);
            u64 u1 = fma2(fma2(pk2(d2f[nb2][2], d2f[nb2][3]), sc2pB, nm2pB), g2p[nb2], b2p[nb2]);
            float2 f0 = upk2(u0), f1 = upk2(u1);
            split2(fmaxf(f0.x, 0.f), fmaxf(f0.y, 0.f), h2h[nb2][0], h2l[nb2][0]);
            split2(fmaxf(f1.x, 0.f), fmaxf(f1.y, 0.f), h2h[nb2][1], h2l[nb2][1]);
        }

        // ---- layer 3 on HMMA (w3 frags in regs, n padded to 8) ----
        float e0 = 0.f, e1 = 0.f, e2 = 0.f, e3 = 0.f;
        mma_bf16(e0,e1,e2,e3, h2h[0][0],h2h[0][1],h2h[1][0],h2h[1][1], w3h[0], w3h[1]);
        mma_bf16(e0,e1,e2,e3, h2h[0][0],h2h[0][1],h2h[1][0],h2h[1][1], w3l[0], w3l[1]);
        mma_bf16(e0,e1,e2,e3, h2l[0][0],h2l[0][1],h2l[1][0],h2l[1][1], w3h[0], w3h[1]);

        // ---- gather channel 2 from quad neighbor, normalize, store ----
        const float c2A = __shfl_down_sync(0xffffffffu, e0, 1);  // D[g][2] from t=1
        const float c2B = __shfl_down_sync(0xffffffffu, e2, 1);  // D[g+8][2]
        if (t == 0) {
            // row g
            {
                const int row = R + g;
                if (row < N) {
                    const float o0 = e0 + bb0, o1 = e1 + bb1, o2 = c2A + bb2;
                    const float inv = 1.0f / fmaxf(sqrtf(o0*o0 + o1*o1 + o2*o2), 1e-12f);
                    const int b  = row / HW;
                    const int hw = row - b * HW;
                    const int ob = (b * 3) * HW + hw;
                    out[ob] = o0 * inv; out[ob + HW] = o1 * inv; out[ob + 2*HW] = o2 * inv;
                }
            }
            // row g+8
            {
                const int row = R + g + 8;
                if (row < N) {
                    const float o0 = e2 + bb0, o1 = e3 + bb1, o2 = c2B + bb2;
                    const float inv = 1.0f / fmaxf(sqrtf(o0*o0 + o1*o1 + o2*o2), 1e-12f);
                    const int b  = row / HW;
                    const int hw = row - b * HW;
                    const int ob = (b * 3) * HW + hw;
                    out[ob] = o0 * inv; out[ob + HW] = o1 * inv; out[ob + 2*HW] = o2 * inv;
                }
            }
        }
    }
}

extern "C" void kernel_launch(void* const* d_in, const int* in_sizes, int n_in,
                              void* d_out, int out_size)
{
    const float* x  = (const float*)d_in[0];
    const float* w1 = (const float*)d_in[1];
    const float* g1 = (const float*)d_in[2];
    const float* b1 = (const float*)d_in[3];
    const float* w2 = (const float*)d_in[4];
    const float* g2 = (const float*)d_in[5];
    const float* b2 = (const float*)d_in[6];
    const float* w3 = (const float*)d_in[7];
    const float* b3 = (const float*)d_in[8];
    const int*   Bp = (const int*)d_in[9];

    const int N       = in_sizes[0] / 64;
    const int ngroups = (N + 15) / 16;
    int blocks = (ngroups + 3) / 4;
    if (blocks > NCTAS) blocks = NCTAS;

    fused_decoder_frag<<<blocks, TPB>>>(
        x, w1, g1, b1, w2, g2, b2, w3, b3, Bp,
        (float*)d_out, N, ngroups);
}

// round 7
// speedup vs baseline: 3.2069x; 1.0237x over previous
#include <cuda_runtime.h>
#include <cuda_bf16.h>

typedef unsigned long long u64;
typedef unsigned int u32;

// ---------------- packed f32x2 helpers ----------------
__device__ __forceinline__ u64 pk2(float lo, float hi) {
    u64 r; asm("mov.b64 %0,{%1,%2};" : "=l"(r) : "f"(lo), "f"(hi)); return r;
}
__device__ __forceinline__ float2 upk2(u64 v) {
    float2 f; asm("mov.b64 {%0,%1},%2;" : "=f"(f.x), "=f"(f.y) : "l"(v)); return f;
}
__device__ __forceinline__ u64 fma2(u64 a, u64 b, u64 c) {
    u64 d; asm("fma.rn.f32x2 %0,%1,%2,%3;" : "=l"(d) : "l"(a), "l"(b), "l"(c)); return d;
}
__device__ __forceinline__ u64 add2(u64 a, u64 b) {
    u64 d; asm("add.rn.f32x2 %0,%1,%2;" : "=l"(d) : "l"(a), "l"(b)); return d;
}

// ---------------- HMMA m16n8k16 row.col f32.bf16.bf16.f32 ----------------
__device__ __forceinline__ void mma_bf16(float& d0, float& d1, float& d2, float& d3,
                                         u32 a0, u32 a1, u32 a2, u32 a3,
                                         u32 b0, u32 b1) {
    asm volatile(
        "mma.sync.aligned.m16n8k16.row.col.f32.bf16.bf16.f32 "
        "{%0,%1,%2,%3}, {%4,%5,%6,%7}, {%8,%9}, {%0,%1,%2,%3};"
        : "+f"(d0), "+f"(d1), "+f"(d2), "+f"(d3)
        : "r"(a0), "r"(a1), "r"(a2), "r"(a3), "r"(b0), "r"(b1));
}

// two floats -> bf16x2 hi (v0 low half, v1 high half) + bf16x2 residual lo
__device__ __forceinline__ void split2(float v0, float v1, u32& h, u32& l) {
    __nv_bfloat162 hb = __float22bfloat162_rn(make_float2(v0, v1));
    h = *reinterpret_cast<u32*>(&hb);
    float r0 = v0 - __bfloat162float(hb.x);
    float r1 = v1 - __bfloat162float(hb.y);
    __nv_bfloat162 lb = __float22bfloat162_rn(make_float2(r0, r1));
    l = *reinterpret_cast<u32*>(&lb);
}

__device__ __forceinline__ u64 shflx(u64 v, int m) {
    return (u64)__shfl_xor_sync(0xffffffffu, (unsigned long long)v, m);
}

#define TPB    128
#define NCTAS  740   // 148 SM * 5

__global__ __launch_bounds__(TPB, 5)
void fused_decoder_frag(const float* __restrict__ x,
                        const float* __restrict__ w1,
                        const float* __restrict__ g1v,
                        const float* __restrict__ b1v,
                        const float* __restrict__ w2,
                        const float* __restrict__ g2v,
                        const float* __restrict__ b2v,
                        const float* __restrict__ w3,
                        const float* __restrict__ b3,
                        const int*   __restrict__ Bp,
                        float*       __restrict__ out,
                        int N, int ngroups)
{
    // w1 B-fragments (bf16 hi/lo), mma layout: [kb*4+nb][lane] = {b0,b1}
    __shared__ __align__(16) uint2 sBH[16][32];
    __shared__ __align__(16) uint2 sBL[16][32];
    // per-lane constant fragment images ([component][lane] -> 16B lane stride, conflict-free)
    __shared__ __align__(16) uint4      sW2H[2][32];   // [kb2][lane] = {nb0_0,nb0_1,nb1_0,nb1_1}
    __shared__ __align__(16) uint4      sW2L[2][32];
    __shared__ __align__(16) uint4      sW3F[32];      // {h0,h1,l0,l1}
    __shared__ __align__(16) ulonglong2 sG1[2][32];    // g1p pairs (nb 0..3)
    __shared__ __align__(16) ulonglong2 sB1[2][32];
    __shared__ __align__(16) ulonglong2 sG2[32];       // g2p pairs (nb2 0..1)
    __shared__ __align__(16) ulonglong2 sB2[32];
    __shared__ float sb3s[3];

    const int tid  = threadIdx.x;
    const int wid  = tid >> 5;
    const int lane = tid & 31;
    const int g    = lane >> 2;        // row-in-group 0..7
    const int t    = lane & 3;         // col-pair selector

    // ---- one-time: stage w1 B-frags ----
    for (int e = tid; e < 512; e += TPB) {
        const int kn = e >> 5, l = e & 31;
        const int kb = kn >> 2, nb = kn & 3;
        const int c  = (l & 3) * 2;
        const int gg = l >> 2;
        const int col  = nb * 8 + gg;
        const int krow = kb * 16 + c;
        u32 h01, l01, h23, l23;
        split2(w1[(krow + 0) * 32 + col], w1[(krow + 1) * 32 + col], h01, l01);
        split2(w1[(krow + 8) * 32 + col], w1[(krow + 9) * 32 + col], h23, l23);
        sBH[kn][l] = make_uint2(h01, h23);
        sBL[kn][l] = make_uint2(l01, l23);
    }

    // ---- one-time: per-lane constant images (warp 0 computes; identical per warp) ----
    if (wid == 0) {
        // w2 (32x16) B-frags
        #pragma unroll
        for (int kb2 = 0; kb2 < 2; kb2++) {
            const int k0 = kb2 * 16 + 2 * t;
            u32 h00, l00, h01_, l01_, h10, l10, h11, l11;
            // nb2 = 0 (cols 0..7)
            split2(w2[k0 * 16 + g],           w2[(k0 + 1) * 16 + g],           h00, l00);
            split2(w2[(k0 + 8) * 16 + g],     w2[(k0 + 9) * 16 + g],           h01_, l01_);
            // nb2 = 1 (cols 8..15)
            split2(w2[k0 * 16 + 8 + g],       w2[(k0 + 1) * 16 + 8 + g],       h10, l10);
            split2(w2[(k0 + 8) * 16 + 8 + g], w2[(k0 + 9) * 16 + 8 + g],       h11, l11);
            sW2H[kb2][lane] = make_uint4(h00, h01_, h10, h11);
            sW2L[kb2][lane] = make_uint4(l00, l01_, l10, l11);
        }
        // w3 (16x3, n padded to 8)
        {
            u32 wh0 = 0u, wh1 = 0u, wl0 = 0u, wl1 = 0u;
            if (g < 3) {
                const int k0 = 2 * t;
                split2(w3[k0 * 3 + g],       w3[(k0 + 1) * 3 + g], wh0, wl0);
                split2(w3[(k0 + 8) * 3 + g], w3[(k0 + 9) * 3 + g], wh1, wl1);
            }
            sW3F[lane] = make_uint4(wh0, wh1, wl0, wl1);
        }
        // gamma/beta packs
        {
            u64 gp[4], bp[4];
            #pragma unroll
            for (int nb = 0; nb < 4; nb++) {
                const int c0 = nb * 8 + 2 * t;
                gp[nb] = pk2(g1v[c0], g1v[c0 + 1]);
                bp[nb] = pk2(b1v[c0], b1v[c0 + 1]);
            }
            sG1[0][lane] = make_ulonglong2(gp[0], gp[1]);
            sG1[1][lane] = make_ulonglong2(gp[2], gp[3]);
            sB1[0][lane] = make_ulonglong2(bp[0], bp[1]);
            sB1[1][lane] = make_ulonglong2(bp[2], bp[3]);
            u64 g2a = pk2(g2v[2 * t],     g2v[2 * t + 1]);
            u64 g2b = pk2(g2v[8 + 2 * t], g2v[8 + 2 * t + 1]);
            u64 b2a = pk2(b2v[2 * t],     b2v[2 * t + 1]);
            u64 b2b = pk2(b2v[8 + 2 * t], b2v[8 + 2 * t + 1]);
            sG2[lane] = make_ulonglong2(g2a, g2b);
            sB2[lane] = make_ulonglong2(b2a, b2b);
        }
        if (lane < 3) sb3s[lane] = b3[lane];
    }
    __syncthreads();

    const int Bv = __ldg(Bp);
    const int HW = N / Bv;

    const int gw0    = blockIdx.x * 4 + wid;
    const int nwarps = gridDim.x * 4;

    #pragma unroll 1
    for (int grp = gw0; grp < ngroups; grp += nwarps) {
        const int R = grp * 16;
        int r0 = R + g;     if (r0 > N - 1) r0 = N - 1;
        int r1 = R + g + 8; if (r1 > N - 1) r1 = N - 1;
        const float* xr0 = x + (size_t)r0 * 64 + 2 * t;
        const float* xr1 = x + (size_t)r1 * 64 + 2 * t;

        // ---- x A-frags (hi/lo) ----
        u32 ah[4][4], al[4][4];
        #pragma unroll
        for (int kb = 0; kb < 4; kb++) {
            const float2 p0 = *(const float2*)(xr0 + kb * 16);
            const float2 p1 = *(const float2*)(xr1 + kb * 16);
            const float2 p2 = *(const float2*)(xr0 + kb * 16 + 8);
            const float2 p3 = *(const float2*)(xr1 + kb * 16 + 8);
            split2(p0.x, p0.y, ah[kb][0], al[kb][0]);
            split2(p1.x, p1.y, ah[kb][1], al[kb][1]);
            split2(p2.x, p2.y, ah[kb][2], al[kb][2]);
            split2(p3.x, p3.y, ah[kb][3], al[kb][3]);
        }

        // ---- layer 1: 4 n-blocks on HMMA ----
        float d1[4][4];
        #pragma unroll
        for (int nb = 0; nb < 4; nb++) {
            float d0 = 0.f, dd1 = 0.f, d2 = 0.f, d3 = 0.f;
            #pragma unroll
            for (int kb = 0; kb < 4; kb++) {
                const uint2 bh = sBH[kb * 4 + nb][lane];
                const uint2 bl = sBL[kb * 4 + nb][lane];
                mma_bf16(d0,dd1,d2,d3, ah[kb][0],ah[kb][1],ah[kb][2],ah[kb][3], bh.x, bh.y);
                mma_bf16(d0,dd1,d2,d3, ah[kb][0],ah[kb][1],ah[kb][2],ah[kb][3], bl.x, bl.y);
                mma_bf16(d0,dd1,d2,d3, al[kb][0],al[kb][1],al[kb][2],al[kb][3], bh.x, bh.y);
            }
            d1[nb][0] = d0; d1[nb][1] = dd1; d1[nb][2] = d2; d1[nb][3] = d3;
        }

        // ---- LN1 in frag layout: quad shuffle stats ----
        u64 ss = 0ull, qq = 0ull;
        #pragma unroll
        for (int nb = 0; nb < 4; nb++) {
            const u64 m0 = pk2(d1[nb][0], d1[nb][2]);
            const u64 m1 = pk2(d1[nb][1], d1[nb][3]);
            ss = add2(ss, add2(m0, m1));
            qq = fma2(m0, m0, fma2(m1, m1, qq));
        }
        ss = add2(ss, shflx(ss, 1)); ss = add2(ss, shflx(ss, 2));
        qq = add2(qq, shflx(qq, 1)); qq = add2(qq, shflx(qq, 2));
        float2 sv = upk2(ss), qv = upk2(qq);
        const float mgA = sv.x * (1.0f/32.0f), mgB = sv.y * (1.0f/32.0f);
        const float scA = rsqrtf(qv.x * (1.0f/32.0f) - mgA * mgA + 1e-5f);
        const float scB = rsqrtf(qv.y * (1.0f/32.0f) - mgB * mgB + 1e-5f);
        const u64 scpA = pk2(scA, scA), nmpA = pk2(-mgA*scA, -mgA*scA);
        const u64 scpB = pk2(scB, scB), nmpB = pk2(-mgB*scB, -mgB*scB);

        // gamma/beta from smem (conflict-free LDS.128)
        const ulonglong2 g1a = sG1[0][lane], g1b = sG1[1][lane];
        const ulonglong2 b1a = sB1[0][lane], b1b = sB1[1][lane];
        const u64 g1p[4] = {g1a.x, g1a.y, g1b.x, g1b.y};
        const u64 b1p[4] = {b1a.x, b1a.y, b1b.x, b1b.y};

        u32 hh[4][2], hl[4][2];
        #pragma unroll
        for (int nb = 0; nb < 4; nb++) {
            u64 u0 = fma2(fma2(pk2(d1[nb][0], d1[nb][1]), scpA, nmpA), g1p[nb], b1p[nb]);
            u64 u1 = fma2(fma2(pk2(d1[nb][2], d1[nb][3]), scpB, nmpB), g1p[nb], b1p[nb]);
            float2 f0 = upk2(u0), f1 = upk2(u1);
            split2(fmaxf(f0.x, 0.f), fmaxf(f0.y, 0.f), hh[nb][0], hl[nb][0]);
            split2(fmaxf(f1.x, 0.f), fmaxf(f1.y, 0.f), hh[nb][1], hl[nb][1]);
        }

        // ---- layer 2 on HMMA (w2 frags from smem) ----
        const uint4 w2h0 = sW2H[0][lane], w2h1 = sW2H[1][lane];
        const uint4 w2l0 = sW2L[0][lane], w2l1 = sW2L[1][lane];

        float d2f[2][4];
        {
            // nb2 = 0
            float d0 = 0.f, dd1 = 0.f, d2 = 0.f, d3 = 0.f;
            mma_bf16(d0,dd1,d2,d3, hh[0][0],hh[0][1],hh[1][0],hh[1][1], w2h0.x, w2h0.y);
            mma_bf16(d0,dd1,d2,d3, hh[0][0],hh[0][1],hh[1][0],hh[1][1], w2l0.x, w2l0.y);
            mma_bf16(d0,dd1,d2,d3, hl[0][0],hl[0][1],hl[1][0],hl[1][1], w2h0.x, w2h0.y);
            mma_bf16(d0,dd1,d2,d3, hh[2][0],hh[2][1],hh[3][0],hh[3][1], w2h1.x, w2h1.y);
            mma_bf16(d0,dd1,d2,d3, hh[2][0],hh[2][1],hh[3][0],hh[3][1], w2l1.x, w2l1.y);
            mma_bf16(d0,dd1,d2,d3, hl[2][0],hl[2][1],hl[3][0],hl[3][1], w2h1.x, w2h1.y);
            d2f[0][0] = d0; d2f[0][1] = dd1; d2f[0][2] = d2; d2f[0][3] = d3;
            // nb2 = 1
            d0 = 0.f; dd1 = 0.f; d2 = 0.f; d3 = 0.f;
            mma_bf16(d0,dd1,d2,d3, hh[0][0],hh[0][1],hh[1][0],hh[1][1], w2h0.z, w2h0.w);
            mma_bf16(d0,dd1,d2,d3, hh[0][0],hh[0][1],hh[1][0],hh[1][1], w2l0.z, w2l0.w);
            mma_bf16(d0,dd1,d2,d3, hl[0][0],hl[0][1],hl[1][0],hl[1][1], w2h0.z, w2h0.w);
            mma_bf16(d0,dd1,d2,d3, hh[2][0],hh[2][1],hh[3][0],hh[3][1], w2h1.z, w2h1.w);
            mma_bf16(d0,dd1,d2,d3, hh[2][0],hh[2][1],hh[3][0],hh[3][1], w2l1.z, w2l1.w);
            mma_bf16(d0,dd1,d2,d3, hl[2][0],hl[2][1],hl[3][0],hl[3][1], w2h1.z, w2h1.w);
            d2f[1][0] = d0; d2f[1][1] = dd1; d2f[1][2] = d2; d2f[1][3] = d3;
        }

        // ---- LN2 ----
        u64 ss2 = 0ull, qq2 = 0ull;
        #pragma unroll
        for (int nb2 = 0; nb2 < 2; nb2++) {
            const u64 m0 = pk2(d2f[nb2][0], d2f[nb2][2]);
            const u64 m1 = pk2(d2f[nb2][1], d2f[nb2][3]);
            ss2 = add2(ss2, add2(m0, m1));
            qq2 = fma2(m0, m0, fma2(m1, m1, qq2));
        }
        ss2 = add2(ss2, shflx(ss2, 1)); ss2 = add2(ss2, shflx(ss2, 2));
        qq2 = add2(qq2, shflx(qq2, 1)); qq2 = add2(qq2, shflx(qq2, 2));
        float2 sv2 = upk2(ss2), qv2 = upk2(qq2);
        const float m2A = sv2.x * (1.0f/16.0f), m2B = sv2.y * (1.0f/16.0f);
        const float s2A = rsqrtf(qv2.x * (1.0f/16.0f) - m2A * m2A + 1e-5f);
        const float s2B = rsqrtf(qv2.y * (1.0f/16.0f) - m2B * m2B + 1e-5f);
        const u64 sc2pA = pk2(s2A, s2A), nm2pA = pk2(-m2A*s2A, -m2A*s2A);
        const u64 sc2pB = pk2(s2B, s2B), nm2pB = pk2(-m2B*s2B, -m2B*s2B);

        const ulonglong2 g2q = sG2[lane], b2q = sB2[lane];
        const u64 g2p[2] = {g2q.x, g2q.y};
        const u64 b2p[2] = {b2q.x, b2q.y};

        u32 h2h[2][2], h2l[2][2];
        #pragma unroll
        for (int nb2 = 0; nb2 < 2; nb2++) {
            u64 u0 = fma2(fma2(pk2(d2f[nb2][0], d2f[nb2][1]), sc2pA, nm2pA), g2p[nb2], b2p[nb2]);
            u64 u1 = fma2(fma2(pk2(d2f[nb2][2], d2f[nb2][3]), sc2pB, nm2pB), g2p[nb2], b2p[nb2]);
            float2 f0 = upk2(u0), f1 = upk2(u1);
            split2(fmaxf(f0.x, 0.f), fmaxf(f0.y, 0.f), h2h[nb2][0], h2l[nb2][0]);
            split2(fmaxf(f1.x, 0.f), fmaxf(f1.y, 0.f), h2h[nb2][1], h2l[nb2][1]);
        }

        // ---- layer 3 on HMMA (w3 frags from smem) ----
        const uint4 w3q = sW3F[lane];
        float e0 = 0.f, e1 = 0.f, e2 = 0.f, e3 = 0.f;
        mma_bf16(e0,e1,e2,e3, h2h[0][0],h2h[0][1],h2h[1][0],h2h[1][1], w3q.x, w3q.y);
        mma_bf16(e0,e1,e2,e3, h2h[0][0],h2h[0][1],h2h[1][0],h2h[1][1], w3q.z, w3q.w);
        mma_bf16(e0,e1,e2,e3, h2l[0][0],h2l[0][1],h2l[1][0],h2l[1][1], w3q.x, w3q.y);

        // ---- gather channel 2 from quad neighbor, normalize, store ----
        const float c2A = __shfl_down_sync(0xffffffffu, e0, 1);  // D[g][2] from t=1
        const float c2B = __shfl_down_sync(0xffffffffu, e2, 1);  // D[g+8][2]
        if (t == 0) {
            const float bb0 = sb3s[0], bb1 = sb3s[1], bb2 = sb3s[2];
            {
                const int row = R + g;
                if (row < N) {
                    const float o0 = e0 + bb0, o1 = e1 + bb1, o2 = c2A + bb2;
                    const float inv = 1.0f / fmaxf(sqrtf(o0*o0 + o1*o1 + o2*o2), 1e-12f);
                    const int b  = row / HW;
                    const int hw = row - b * HW;
                    const int ob = (b * 3) * HW + hw;
                    out[ob] = o0 * inv; out[ob + HW] = o1 * inv; out[ob + 2*HW] = o2 * inv;
                }
            }
            {
                const int row = R + g + 8;
                if (row < N) {
                    const float o0 = e2 + bb0, o1 = e3 + bb1, o2 = c2B + bb2;
                    const float inv = 1.0f / fmaxf(sqrtf(o0*o0 + o1*o1 + o2*o2), 1e-12f);
                    const int b  = row / HW;
                    const int hw = row - b * HW;
                    const int ob = (b * 3) * HW + hw;
                    out[ob] = o0 * inv; out[ob + HW] = o1 * inv; out[ob + 2*HW] = o2 * inv;
                }
            }
        }
    }
}

extern "C" void kernel_launch(void* const* d_in, const int* in_sizes, int n_in,
                              void* d_out, int out_size)
{
    const float* x  = (const float*)d_in[0];
    const float* w1 = (const float*)d_in[1];
    const float* g1 = (const float*)d_in[2];
    const float* b1 = (const float*)d_in[3];
    const float* w2 = (const float*)d_in[4];
    const float* g2 = (const float*)d_in[5];
    const float* b2 = (const float*)d_in[6];
    const float* w3 = (const float*)d_in[7];
    const float* b3 = (const float*)d_in[8];
    const int*   Bp = (const int*)d_in[9];

    const int N       = in_sizes[0] / 64;
    const int ngroups = (N + 15) / 16;
    int blocks = (ngroups + 3) / 4;
    if (blocks > NCTAS) blocks = NCTAS;

    fused_decoder_frag<<<blocks, TPB>>>(
        x, w1, g1, b1, w2, g2, b2, w3, b3, Bp,
        (float*)d_out, N, ngroups);
}

// round 8
// speedup vs baseline: 3.4093x; 1.0631x over previous
#include <cuda_runtime.h>
#include <cuda_bf16.h>

typedef unsigned long long u64;
typedef unsigned int u32;

// ---------------- packed f32x2 helpers ----------------
__device__ __forceinline__ u64 pk2(float lo, float hi) {
    u64 r; asm("mov.b64 %0,{%1,%2};" : "=l"(r) : "f"(lo), "f"(hi)); return r;
}
__device__ __forceinline__ float2 upk2(u64 v) {
    float2 f; asm("mov.b64 {%0,%1},%2;" : "=f"(f.x), "=f"(f.y) : "l"(v)); return f;
}
__device__ __forceinline__ u64 fma2(u64 a, u64 b, u64 c) {
    u64 d; asm("fma.rn.f32x2 %0,%1,%2,%3;" : "=l"(d) : "l"(a), "l"(b), "l"(c)); return d;
}
__device__ __forceinline__ u64 add2(u64 a, u64 b) {
    u64 d; asm("add.rn.f32x2 %0,%1,%2;" : "=l"(d) : "l"(a), "l"(b)); return d;
}

// ---------------- HMMA m16n8k16 row.col f32.bf16.bf16.f32 ----------------
__device__ __forceinline__ void mma_bf16(float& d0, float& d1, float& d2, float& d3,
                                         u32 a0, u32 a1, u32 a2, u32 a3,
                                         u32 b0, u32 b1) {
    asm volatile(
        "mma.sync.aligned.m16n8k16.row.col.f32.bf16.bf16.f32 "
        "{%0,%1,%2,%3}, {%4,%5,%6,%7}, {%8,%9}, {%0,%1,%2,%3};"
        : "+f"(d0), "+f"(d1), "+f"(d2), "+f"(d3)
        : "r"(a0), "r"(a1), "r"(a2), "r"(a3), "r"(b0), "r"(b1));
}

// two floats -> bf16x2 hi + bf16x2 residual lo.
// bf16->f32 reconstruction via bit ops (exact, lat-4 LOP instead of CVT);
// both residual subs in ONE packed fma (x * -1 + v == v - x).
__device__ __forceinline__ void split2(float v0, float v1, u32& h, u32& l) {
    __nv_bfloat162 hb = __float22bfloat162_rn(make_float2(v0, v1));
    h = *reinterpret_cast<u32*>(&hb);
    const float f0 = __uint_as_float(h << 16);
    const float f1 = __uint_as_float(h & 0xffff0000u);
    const u64 r = fma2(pk2(f0, f1), 0xBF800000BF800000ull /*(-1,-1)*/, pk2(v0, v1));
    const float2 rf = upk2(r);
    __nv_bfloat162 lb = __float22bfloat162_rn(make_float2(rf.x, rf.y));
    l = *reinterpret_cast<u32*>(&lb);
}

__device__ __forceinline__ u64 shflx(u64 v, int m) {
    return (u64)__shfl_xor_sync(0xffffffffu, (unsigned long long)v, m);
}

#define TPB    128
#define NCTAS  888   // 148 SM * 6

__global__ __launch_bounds__(TPB, 6)
void fused_decoder_frag(const float* __restrict__ x,
                        const float* __restrict__ w1,
                        const float* __restrict__ g1v,
                        const float* __restrict__ b1v,
                        const float* __restrict__ w2,
                        const float* __restrict__ g2v,
                        const float* __restrict__ b2v,
                        const float* __restrict__ w3,
                        const float* __restrict__ b3,
                        const int*   __restrict__ Bp,
                        float*       __restrict__ out,
                        int N, int ngroups)
{
    // w1 B-fragments (bf16 hi/lo), mma layout: [kb*4+nb][lane] = {b0,b1}
    __shared__ __align__(16) uint2 sBH[16][32];
    __shared__ __align__(16) uint2 sBL[16][32];
    // per-lane constant fragment images ([component][lane] -> 16B lane stride, conflict-free)
    __shared__ __align__(16) uint4      sW2H[2][32];
    __shared__ __align__(16) uint4      sW2L[2][32];
    __shared__ __align__(16) uint4      sW3F[32];
    __shared__ __align__(16) ulonglong2 sG1[2][32];
    __shared__ __align__(16) ulonglong2 sB1[2][32];
    __shared__ __align__(16) ulonglong2 sG2[32];
    __shared__ __align__(16) ulonglong2 sB2[32];
    __shared__ float sb3s[3];

    const int tid  = threadIdx.x;
    const int wid  = tid >> 5;
    const int lane = tid & 31;
    const int g    = lane >> 2;        // row-in-group 0..7
    const int t    = lane & 3;         // col-pair selector

    // ---- one-time: stage w1 B-frags ----
    for (int e = tid; e < 512; e += TPB) {
        const int kn = e >> 5, l = e & 31;
        const int kb = kn >> 2, nb = kn & 3;
        const int c  = (l & 3) * 2;
        const int gg = l >> 2;
        const int col  = nb * 8 + gg;
        const int krow = kb * 16 + c;
        u32 h01, l01, h23, l23;
        split2(w1[(krow + 0) * 32 + col], w1[(krow + 1) * 32 + col], h01, l01);
        split2(w1[(krow + 8) * 32 + col], w1[(krow + 9) * 32 + col], h23, l23);
        sBH[kn][l] = make_uint2(h01, h23);
        sBL[kn][l] = make_uint2(l01, l23);
    }

    // ---- one-time: per-lane constant images (warp 0 computes) ----
    if (wid == 0) {
        #pragma unroll
        for (int kb2 = 0; kb2 < 2; kb2++) {
            const int k0 = kb2 * 16 + 2 * t;
            u32 h00, l00, h01_, l01_, h10, l10, h11, l11;
            split2(w2[k0 * 16 + g],           w2[(k0 + 1) * 16 + g],           h00, l00);
            split2(w2[(k0 + 8) * 16 + g],     w2[(k0 + 9) * 16 + g],           h01_, l01_);
            split2(w2[k0 * 16 + 8 + g],       w2[(k0 + 1) * 16 + 8 + g],       h10, l10);
            split2(w2[(k0 + 8) * 16 + 8 + g], w2[(k0 + 9) * 16 + 8 + g],       h11, l11);
            sW2H[kb2][lane] = make_uint4(h00, h01_, h10, h11);
            sW2L[kb2][lane] = make_uint4(l00, l01_, l10, l11);
        }
        {
            u32 wh0 = 0u, wh1 = 0u, wl0 = 0u, wl1 = 0u;
            if (g < 3) {
                const int k0 = 2 * t;
                split2(w3[k0 * 3 + g],       w3[(k0 + 1) * 3 + g], wh0, wl0);
                split2(w3[(k0 + 8) * 3 + g], w3[(k0 + 9) * 3 + g], wh1, wl1);
            }
            sW3F[lane] = make_uint4(wh0, wh1, wl0, wl1);
        }
        {
            u64 gp[4], bp[4];
            #pragma unroll
            for (int nb = 0; nb < 4; nb++) {
                const int c0 = nb * 8 + 2 * t;
                gp[nb] = pk2(g1v[c0], g1v[c0 + 1]);
                bp[nb] = pk2(b1v[c0], b1v[c0 + 1]);
            }
            sG1[0][lane] = make_ulonglong2(gp[0], gp[1]);
            sG1[1][lane] = make_ulonglong2(gp[2], gp[3]);
            sB1[0][lane] = make_ulonglong2(bp[0], bp[1]);
            sB1[1][lane] = make_ulonglong2(bp[2], bp[3]);
            sG2[lane] = make_ulonglong2(pk2(g2v[2*t], g2v[2*t+1]), pk2(g2v[8+2*t], g2v[8+2*t+1]));
            sB2[lane] = make_ulonglong2(pk2(b2v[2*t], b2v[2*t+1]), pk2(b2v[8+2*t], b2v[8+2*t+1]));
        }
        if (lane < 3) sb3s[lane] = b3[lane];
    }
    __syncthreads();

    const int Bv = __ldg(Bp);
    const int HW = N / Bv;
    const float bb0 = sb3s[0], bb1 = sb3s[1], bb2 = sb3s[2];

    const int gw0    = blockIdx.x * 4 + wid;
    const int nwarps = gridDim.x * 4;

    #pragma unroll 1
    for (int grp = gw0; grp < ngroups; grp += nwarps) {
        const int R = grp * 16;
        int r0 = R + g;     if (r0 > N - 1) r0 = N - 1;
        int r1 = R + g + 8; if (r1 > N - 1) r1 = N - 1;
        const float* xr0 = x + (size_t)r0 * 64 + 2 * t;
        const float* xr1 = x + (size_t)r1 * 64 + 2 * t;

        // ---- x A-frags (hi/lo) ----
        u32 ah[4][4], al[4][4];
        #pragma unroll
        for (int kb = 0; kb < 4; kb++) {
            const float2 p0 = *(const float2*)(xr0 + kb * 16);
            const float2 p1 = *(const float2*)(xr1 + kb * 16);
            const float2 p2 = *(const float2*)(xr0 + kb * 16 + 8);
            const float2 p3 = *(const float2*)(xr1 + kb * 16 + 8);
            split2(p0.x, p0.y, ah[kb][0], al[kb][0]);
            split2(p1.x, p1.y, ah[kb][1], al[kb][1]);
            split2(p2.x, p2.y, ah[kb][2], al[kb][2]);
            split2(p3.x, p3.y, ah[kb][3], al[kb][3]);
        }

        // ---- layer 1: 4 n-blocks on HMMA ----
        float d1[4][4];
        #pragma unroll
        for (int nb = 0; nb < 4; nb++) {
            float d0 = 0.f, dd1 = 0.f, d2 = 0.f, d3 = 0.f;
            #pragma unroll
            for (int kb = 0; kb < 4; kb++) {
                const uint2 bh = sBH[kb * 4 + nb][lane];
                const uint2 bl = sBL[kb * 4 + nb][lane];
                mma_bf16(d0,dd1,d2,d3, ah[kb][0],ah[kb][1],ah[kb][2],ah[kb][3], bh.x, bh.y);
                mma_bf16(d0,dd1,d2,d3, ah[kb][0],ah[kb][1],ah[kb][2],ah[kb][3], bl.x, bl.y);
                mma_bf16(d0,dd1,d2,d3, al[kb][0],al[kb][1],al[kb][2],al[kb][3], bh.x, bh.y);
            }
            d1[nb][0] = d0; d1[nb][1] = dd1; d1[nb][2] = d2; d1[nb][3] = d3;
        }

        // ---- LN1 in frag layout: quad shuffle stats ----
        u64 ss = 0ull, qq = 0ull;
        #pragma unroll
        for (int nb = 0; nb < 4; nb++) {
            const u64 m0 = pk2(d1[nb][0], d1[nb][2]);
            const u64 m1 = pk2(d1[nb][1], d1[nb][3]);
            ss = add2(ss, add2(m0, m1));
            qq = fma2(m0, m0, fma2(m1, m1, qq));
        }
        ss = add2(ss, shflx(ss, 1)); ss = add2(ss, shflx(ss, 2));
        qq = add2(qq, shflx(qq, 1)); qq = add2(qq, shflx(qq, 2));
        float2 sv = upk2(ss), qv = upk2(qq);
        const float mgA = sv.x * (1.0f/32.0f), mgB = sv.y * (1.0f/32.0f);
        const float scA = rsqrtf(qv.x * (1.0f/32.0f) - mgA * mgA + 1e-5f);
        const float scB = rsqrtf(qv.y * (1.0f/32.0f) - mgB * mgB + 1e-5f);
        const u64 scpA = pk2(scA, scA), nmpA = pk2(-mgA*scA, -mgA*scA);
        const u64 scpB = pk2(scB, scB), nmpB = pk2(-mgB*scB, -mgB*scB);

        const ulonglong2 g1a = sG1[0][lane], g1b = sG1[1][lane];
        const ulonglong2 b1a = sB1[0][lane], b1b = sB1[1][lane];
        const u64 g1p[4] = {g1a.x, g1a.y, g1b.x, g1b.y};
        const u64 b1p[4] = {b1a.x, b1a.y, b1b.x, b1b.y};

        u32 hh[4][2], hl[4][2];
        #pragma unroll
        for (int nb = 0; nb < 4; nb++) {
            u64 u0 = fma2(fma2(pk2(d1[nb][0], d1[nb][1]), scpA, nmpA), g1p[nb], b1p[nb]);
            u64 u1 = fma2(fma2(pk2(d1[nb][2], d1[nb][3]), scpB, nmpB), g1p[nb], b1p[nb]);
            float2 f0 = upk2(u0), f1 = upk2(u1);
            split2(fmaxf(f0.x, 0.f), fmaxf(f0.y, 0.f), hh[nb][0], hl[nb][0]);
            split2(fmaxf(f1.x, 0.f), fmaxf(f1.y, 0.f), hh[nb][1], hl[nb][1]);
        }

        // ---- layer 2 on HMMA (w2 frags from smem) ----
        const uint4 w2h0 = sW2H[0][lane], w2h1 = sW2H[1][lane];
        const uint4 w2l0 = sW2L[0][lane], w2l1 = sW2L[1][lane];

        float d2f[2][4];
        {
            float d0 = 0.f, dd1 = 0.f, d2 = 0.f, d3 = 0.f;
            mma_bf16(d0,dd1,d2,d3, hh[0][0],hh[0][1],hh[1][0],hh[1][1], w2h0.x, w2h0.y);
            mma_bf16(d0,dd1,d2,d3, hh[0][0],hh[0][1],hh[1][0],hh[1][1], w2l0.x, w2l0.y);
            mma_bf16(d0,dd1,d2,d3, hl[0][0],hl[0][1],hl[1][0],hl[1][1], w2h0.x, w2h0.y);
            mma_bf16(d0,dd1,d2,d3, hh[2][0],hh[2][1],hh[3][0],hh[3][1], w2h1.x, w2h1.y);
            mma_bf16(d0,dd1,d2,d3, hh[2][0],hh[2][1],hh[3][0],hh[3][1], w2l1.x, w2l1.y);
            mma_bf16(d0,dd1,d2,d3, hl[2][0],hl[2][1],hl[3][0],hl[3][1], w2h1.x, w2h1.y);
            d2f[0][0] = d0; d2f[0][1] = dd1; d2f[0][2] = d2; d2f[0][3] = d3;
            d0 = 0.f; dd1 = 0.f; d2 = 0.f; d3 = 0.f;
            mma_bf16(d0,dd1,d2,d3, hh[0][0],hh[0][1],hh[1][0],hh[1][1], w2h0.z, w2h0.w);
            mma_bf16(d0,dd1,d2,d3, hh[0][0],hh[0][1],hh[1][0],hh[1][1], w2l0.z, w2l0.w);
            mma_bf16(d0,dd1,d2,d3, hl[0][0],hl[0][1],hl[1][0],hl[1][1], w2h0.z, w2h0.w);
            mma_bf16(d0,dd1,d2,d3, hh[2][0],hh[2][1],hh[3][0],hh[3][1], w2h1.z, w2h1.w);
            mma_bf16(d0,dd1,d2,d3, hh[2][0],hh[2][1],hh[3][0],hh[3][1], w2l1.z, w2l1.w);
            mma_bf16(d0,dd1,d2,d3, hl[2][0],hl[2][1],hl[3][0],hl[3][1], w2h1.z, w2h1.w);
            d2f[1][0] = d0; d2f[1][1] = dd1; d2f[1][2] = d2; d2f[1][3] = d3;
        }

        // ---- LN2 ----
        u64 ss2 = 0ull, qq2 = 0ull;
        #pragma unroll
        for (int nb2 = 0; nb2 < 2; nb2++) {
            const u64 m0 = pk2(d2f[nb2][0], d2f[nb2][2]);
            const u64 m1 = pk2(d2f[nb2][1], d2f[nb2][3]);
            ss2 = add2(ss2, add2(m0, m1));
            qq2 = fma2(m0, m0, fma2(m1, m1, qq2));
        }
        ss2 = add2(ss2, shflx(ss2, 1)); ss2 = add2(ss2, shflx(ss2, 2));
        qq2 = add2(qq2, shflx(qq2, 1)); qq2 = add2(qq2, shflx(qq2, 2));
        float2 sv2 = upk2(ss2), qv2 = upk2(qq2);
        const float m2A = sv2.x * (1.0f/16.0f), m2B = sv2.y * (1.0f/16.0f);
        const float s2A = rsqrtf(qv2.x * (1.0f/16.0f) - m2A * m2A + 1e-5f);
        const float s2B = rsqrtf(qv2.y * (1.0f/16.0f) - m2B * m2B + 1e-5f);
        const u64 sc2pA = pk2(s2A, s2A), nm2pA = pk2(-m2A*s2A, -m2A*s2A);
        const u64 sc2pB = pk2(s2B, s2B), nm2pB = pk2(-m2B*s2B, -m2B*s2B);

        const ulonglong2 g2q = sG2[lane], b2q = sB2[lane];
        const u64 g2p[2] = {g2q.x, g2q.y};
        const u64 b2p[2] = {b2q.x, b2q.y};

        u32 h2h[2][2], h2l[2][2];
        #pragma unroll
        for (int nb2 = 0; nb2 < 2; nb2++) {
            u64 u0 = fma2(fma2(pk2(d2f[nb2][0], d2f[nb2][1]), sc2pA, nm2pA), g2p[nb2], b2p[nb2]);
            u64 u1 = fma2(fma2(pk2(d2f[nb2][2], d2f[nb2][3]), sc2pB, nm2pB), g2p[nb2], b2p[nb2]);
            float2 f0 = upk2(u0), f1 = upk2(u1);
            split2(fmaxf(f0.x, 0.f), fmaxf(f0.y, 0.f), h2h[nb2][0], h2l[nb2][0]);
            split2(fmaxf(f1.x, 0.f), fmaxf(f1.y, 0.f), h2h[nb2][1], h2l[nb2][1]);
        }

        // ---- layer 3 on HMMA ----
        const uint4 w3q = sW3F[lane];
        float e0 = 0.f, e1 = 0.f, e2 = 0.f, e3 = 0.f;
        mma_bf16(e0,e1,e2,e3, h2h[0][0],h2h[0][1],h2h[1][0],h2h[1][1], w3q.x, w3q.y);
        mma_bf16(e0,e1,e2,e3, h2h[0][0],h2h[0][1],h2h[1][0],h2h[1][1], w3q.z, w3q.w);
        mma_bf16(e0,e1,e2,e3, h2l[0][0],h2l[0][1],h2l[1][0],h2l[1][1], w3q.x, w3q.y);

        // ---- gather channel 2 from quad neighbor, normalize, store ----
        const float c2A = __shfl_down_sync(0xffffffffu, e0, 1);
        const float c2B = __shfl_down_sync(0xffffffffu, e2, 1);
        if (t == 0) {
            {
                const int row = R + g;
                if (row < N) {
                    const float o0 = e0 + bb0, o1 = e1 + bb1, o2 = c2A + bb2;
                    const float inv = 1.0f / fmaxf(sqrtf(o0*o0 + o1*o1 + o2*o2), 1e-12f);
                    const int b  = row / HW;
                    const int hw = row - b * HW;
                    const int ob = (b * 3) * HW + hw;
                    out[ob] = o0 * inv; out[ob + HW] = o1 * inv; out[ob + 2*HW] = o2 * inv;
                }
            }
            {
                const int row = R + g + 8;
                if (row < N) {
                    const float o0 = e2 + bb0, o1 = e3 + bb1, o2 = c2B + bb2;
                    const float inv = 1.0f / fmaxf(sqrtf(o0*o0 + o1*o1 + o2*o2), 1e-12f);
                    const int b  = row / HW;
                    const int hw = row - b * HW;
                    const int ob = (b * 3) * HW + hw;
                    out[ob] = o0 * inv; out[ob + HW] = o1 * inv; out[ob + 2*HW] = o2 * inv;
                }
            }
        }
    }
}

extern "C" void kernel_launch(void* const* d_in, const int* in_sizes, int n_in,
                              void* d_out, int out_size)
{
    const float* x  = (const float*)d_in[0];
    const float* w1 = (const float*)d_in[1];
    const float* g1 = (const float*)d_in[2];
    const float* b1 = (const float*)d_in[3];
    const float* w2 = (const float*)d_in[4];
    const float* g2 = (const float*)d_in[5];
    const float* b2 = (const float*)d_in[6];
    const float* w3 = (const float*)d_in[7];
    const float* b3 = (const float*)d_in[8];
    const int*   Bp = (const int*)d_in[9];

    const int N       = in_sizes[0] / 64;
    const int ngroups = (N + 15) / 16;
    int blocks = (ngroups + 3) / 4;
    if (blocks > NCTAS) blocks = NCTAS;

    fused_decoder_frag<<<blocks, TPB>>>(
        x, w1, g1, b1, w2, g2, b2, w3, b3, Bp,
        (float*)d_out, N, ngroups);
}

// round 9
// speedup vs baseline: 3.5690x; 1.0469x over previous
#include <cuda_runtime.h>
#include <cuda_bf16.h>

typedef unsigned long long u64;
typedef unsigned int u32;

// ---------------- packed f32x2 helpers ----------------
__device__ __forceinline__ u64 pk2(float lo, float hi) {
    u64 r; asm("mov.b64 %0,{%1,%2};" : "=l"(r) : "f"(lo), "f"(hi)); return r;
}
__device__ __forceinline__ float2 upk2(u64 v) {
    float2 f; asm("mov.b64 {%0,%1},%2;" : "=f"(f.x), "=f"(f.y) : "l"(v)); return f;
}
__device__ __forceinline__ u64 fma2(u64 a, u64 b, u64 c) {
    u64 d; asm("fma.rn.f32x2 %0,%1,%2,%3;" : "=l"(d) : "l"(a), "l"(b), "l"(c)); return d;
}
__device__ __forceinline__ u64 add2(u64 a, u64 b) {
    u64 d; asm("add.rn.f32x2 %0,%1,%2;" : "=l"(d) : "l"(a), "l"(b)); return d;
}

// ---------------- HMMA m16n8k16 row.col f32.bf16.bf16.f32 ----------------
__device__ __forceinline__ void mma_bf16(float& d0, float& d1, float& d2, float& d3,
                                         u32 a0, u32 a1, u32 a2, u32 a3,
                                         u32 b0, u32 b1) {
    asm volatile(
        "mma.sync.aligned.m16n8k16.row.col.f32.bf16.bf16.f32 "
        "{%0,%1,%2,%3}, {%4,%5,%6,%7}, {%8,%9}, {%0,%1,%2,%3};"
        : "+f"(d0), "+f"(d1), "+f"(d2), "+f"(d3)
        : "r"(a0), "r"(a1), "r"(a2), "r"(a3), "r"(b0), "r"(b1));
}

// two floats -> bf16x2 hi + bf16x2 residual lo (bit-op reconstruction + packed fma)
__device__ __forceinline__ void split2(float v0, float v1, u32& h, u32& l) {
    __nv_bfloat162 hb = __float22bfloat162_rn(make_float2(v0, v1));
    h = *reinterpret_cast<u32*>(&hb);
    const float f0 = __uint_as_float(h << 16);
    const float f1 = __uint_as_float(h & 0xffff0000u);
    const u64 r = fma2(pk2(f0, f1), 0xBF800000BF800000ull /*(-1,-1)*/, pk2(v0, v1));
    const float2 rf = upk2(r);
    __nv_bfloat162 lb = __float22bfloat162_rn(make_float2(rf.x, rf.y));
    l = *reinterpret_cast<u32*>(&lb);
}

__device__ __forceinline__ u64 shflx(u64 v, int m) {
    return (u64)__shfl_xor_sync(0xffffffffu, (unsigned long long)v, m);
}

#define TPB    128
#define NCTAS  888   // 148 SM * 6

// k-axis permutation: sigma(2t+j) = 4t+j, sigma(8+2t+j) = 4t+2+j, applied to BOTH
// x columns and w1 rows within each k16 block. Lane t's A-frag elements become the
// contiguous source cols [4t, 4t+3] -> ONE aligned float4 per (row, k-block)
// instead of two scattered float2s. w1 staging absorbs sigma at zero runtime cost.
__global__ __launch_bounds__(TPB, 6)
void fused_decoder_frag(const float* __restrict__ x,
                        const float* __restrict__ w1,
                        const float* __restrict__ g1v,
                        const float* __restrict__ b1v,
                        const float* __restrict__ w2,
                        const float* __restrict__ g2v,
                        const float* __restrict__ b2v,
                        const float* __restrict__ w3,
                        const float* __restrict__ b3,
                        const int*   __restrict__ Bp,
                        float*       __restrict__ out,
                        int N, int ngroups)
{
    // w1 B-fragments (bf16 hi/lo), mma layout: [kb*4+nb][lane] = {b0,b1}
    __shared__ __align__(16) uint2 sBH[16][32];
    __shared__ __align__(16) uint2 sBL[16][32];
    // per-lane constant fragment images ([component][lane] -> 16B lane stride, conflict-free)
    __shared__ __align__(16) uint4      sW2H[2][32];
    __shared__ __align__(16) uint4      sW2L[2][32];
    __shared__ __align__(16) uint4      sW3F[32];
    __shared__ __align__(16) ulonglong2 sG1[2][32];
    __shared__ __align__(16) ulonglong2 sB1[2][32];
    __shared__ __align__(16) ulonglong2 sG2[32];
    __shared__ __align__(16) ulonglong2 sB2[32];
    __shared__ float sb3s[3];

    const int tid  = threadIdx.x;
    const int wid  = tid >> 5;
    const int lane = tid & 31;
    const int g    = lane >> 2;        // row-in-group 0..7
    const int t    = lane & 3;         // col-quad selector

    // ---- one-time: stage w1 B-frags with the k permutation baked in ----
    // lane tq needs: b0 = w1 src rows {4tq, 4tq+1}, b1 = {4tq+2, 4tq+3} (per k16 block)
    for (int e = tid; e < 512; e += TPB) {
        const int kn = e >> 5, l = e & 31;
        const int kb = kn >> 2, nb = kn & 3;
        const int c4 = (l & 3) * 4;
        const int gg = l >> 2;
        const int col  = nb * 8 + gg;
        const int krow = kb * 16 + c4;
        u32 h01, l01, h23, l23;
        split2(w1[(krow + 0) * 32 + col], w1[(krow + 1) * 32 + col], h01, l01);
        split2(w1[(krow + 2) * 32 + col], w1[(krow + 3) * 32 + col], h23, l23);
        sBH[kn][l] = make_uint2(h01, h23);
        sBL[kn][l] = make_uint2(l01, l23);
    }

    // ---- one-time: per-lane constant images (warp 0 computes) ----
    if (wid == 0) {
        #pragma unroll
        for (int kb2 = 0; kb2 < 2; kb2++) {
            const int k0 = kb2 * 16 + 2 * t;
            u32 h00, l00, h01_, l01_, h10, l10, h11, l11;
            split2(w2[k0 * 16 + g],           w2[(k0 + 1) * 16 + g],           h00, l00);
            split2(w2[(k0 + 8) * 16 + g],     w2[(k0 + 9) * 16 + g],           h01_, l01_);
            split2(w2[k0 * 16 + 8 + g],       w2[(k0 + 1) * 16 + 8 + g],       h10, l10);
            split2(w2[(k0 + 8) * 16 + 8 + g], w2[(k0 + 9) * 16 + 8 + g],       h11, l11);
            sW2H[kb2][lane] = make_uint4(h00, h01_, h10, h11);
            sW2L[kb2][lane] = make_uint4(l00, l01_, l10, l11);
        }
        {
            u32 wh0 = 0u, wh1 = 0u, wl0 = 0u, wl1 = 0u;
            if (g < 3) {
                const int k0 = 2 * t;
                split2(w3[k0 * 3 + g],       w3[(k0 + 1) * 3 + g], wh0, wl0);
                split2(w3[(k0 + 8) * 3 + g], w3[(k0 + 9) * 3 + g], wh1, wl1);
            }
            sW3F[lane] = make_uint4(wh0, wh1, wl0, wl1);
        }
        {
            u64 gp[4], bp[4];
            #pragma unroll
            for (int nb = 0; nb < 4; nb++) {
                const int c0 = nb * 8 + 2 * t;
                gp[nb] = pk2(g1v[c0], g1v[c0 + 1]);
                bp[nb] = pk2(b1v[c0], b1v[c0 + 1]);
            }
            sG1[0][lane] = make_ulonglong2(gp[0], gp[1]);
            sG1[1][lane] = make_ulonglong2(gp[2], gp[3]);
            sB1[0][lane] = make_ulonglong2(bp[0], bp[1]);
            sB1[1][lane] = make_ulonglong2(bp[2], bp[3]);
            sG2[lane] = make_ulonglong2(pk2(g2v[2*t], g2v[2*t+1]), pk2(g2v[8+2*t], g2v[8+2*t+1]));
            sB2[lane] = make_ulonglong2(pk2(b2v[2*t], b2v[2*t+1]), pk2(b2v[8+2*t], b2v[8+2*t+1]));
        }
        if (lane < 3) sb3s[lane] = b3[lane];
    }
    __syncthreads();

    const int Bv = __ldg(Bp);
    const int HW = N / Bv;
    const float bb0 = sb3s[0], bb1 = sb3s[1], bb2 = sb3s[2];

    const int gw0    = blockIdx.x * 4 + wid;
    const int nwarps = gridDim.x * 4;

    #pragma unroll 1
    for (int grp = gw0; grp < ngroups; grp += nwarps) {
        const int R = grp * 16;
        int r0 = R + g;     if (r0 > N - 1) r0 = N - 1;
        int r1 = R + g + 8; if (r1 > N - 1) r1 = N - 1;
        const float4* xr0 = (const float4*)(x + (size_t)r0 * 64 + 4 * t);  // 16B aligned
        const float4* xr1 = (const float4*)(x + (size_t)r1 * 64 + 4 * t);

        // ---- x A-frags (hi/lo): ONE float4 per (row, k-block), permuted k ----
        u32 ah[4][4], al[4][4];
        #pragma unroll
        for (int kb = 0; kb < 4; kb++) {
            const float4 q0 = xr0[kb * 4];   // cols 16kb + 4t .. +3 of row r0
            const float4 q1 = xr1[kb * 4];
            split2(q0.x, q0.y, ah[kb][0], al[kb][0]);   // a0: frag-k {2t,2t+1}
            split2(q1.x, q1.y, ah[kb][1], al[kb][1]);   // a1: row g+8
            split2(q0.z, q0.w, ah[kb][2], al[kb][2]);   // a2: frag-k {2t+8,2t+9}
            split2(q1.z, q1.w, ah[kb][3], al[kb][3]);   // a3
        }

        // ---- layer 1: 4 n-blocks on HMMA ----
        float d1[4][4];
        #pragma unroll
        for (int nb = 0; nb < 4; nb++) {
            float d0 = 0.f, dd1 = 0.f, d2 = 0.f, d3 = 0.f;
            #pragma unroll
            for (int kb = 0; kb < 4; kb++) {
                const uint2 bh = sBH[kb * 4 + nb][lane];
                const uint2 bl = sBL[kb * 4 + nb][lane];
                mma_bf16(d0,dd1,d2,d3, ah[kb][0],ah[kb][1],ah[kb][2],ah[kb][3], bh.x, bh.y);
                mma_bf16(d0,dd1,d2,d3, ah[kb][0],ah[kb][1],ah[kb][2],ah[kb][3], bl.x, bl.y);
                mma_bf16(d0,dd1,d2,d3, al[kb][0],al[kb][1],al[kb][2],al[kb][3], bh.x, bh.y);
            }
            d1[nb][0] = d0; d1[nb][1] = dd1; d1[nb][2] = d2; d1[nb][3] = d3;
        }

        // ---- LN1 in frag layout: quad shuffle stats ----
        u64 ss = 0ull, qq = 0ull;
        #pragma unroll
        for (int nb = 0; nb < 4; nb++) {
            const u64 m0 = pk2(d1[nb][0], d1[nb][2]);
            const u64 m1 = pk2(d1[nb][1], d1[nb][3]);
            ss = add2(ss, add2(m0, m1));
            qq = fma2(m0, m0, fma2(m1, m1, qq));
        }
        ss = add2(ss, shflx(ss, 1)); ss = add2(ss, shflx(ss, 2));
        qq = add2(qq, shflx(qq, 1)); qq = add2(qq, shflx(qq, 2));
        float2 sv = upk2(ss), qv = upk2(qq);
        const float mgA = sv.x * (1.0f/32.0f), mgB = sv.y * (1.0f/32.0f);
        const float scA = rsqrtf(qv.x * (1.0f/32.0f) - mgA * mgA + 1e-5f);
        const float scB = rsqrtf(qv.y * (1.0f/32.0f) - mgB * mgB + 1e-5f);
        const u64 scpA = pk2(scA, scA), nmpA = pk2(-mgA*scA, -mgA*scA);
        const u64 scpB = pk2(scB, scB), nmpB = pk2(-mgB*scB, -mgB*scB);

        const ulonglong2 g1a = sG1[0][lane], g1b = sG1[1][lane];
        const ulonglong2 b1a = sB1[0][lane], b1b = sB1[1][lane];
        const u64 g1p[4] = {g1a.x, g1a.y, g1b.x, g1b.y};
        const u64 b1p[4] = {b1a.x, b1a.y, b1b.x, b1b.y};

        u32 hh[4][2], hl[4][2];
        #pragma unroll
        for (int nb = 0; nb < 4; nb++) {
            u64 u0 = fma2(fma2(pk2(d1[nb][0], d1[nb][1]), scpA, nmpA), g1p[nb], b1p[nb]);
            u64 u1 = fma2(fma2(pk2(d1[nb][2], d1[nb][3]), scpB, nmpB), g1p[nb], b1p[nb]);
            float2 f0 = upk2(u0), f1 = upk2(u1);
            split2(fmaxf(f0.x, 0.f), fmaxf(f0.y, 0.f), hh[nb][0], hl[nb][0]);
            split2(fmaxf(f1.x, 0.f), fmaxf(f1.y, 0.f), hh[nb][1], hl[nb][1]);
        }

        // ---- layer 2 on HMMA (w2 frags from smem) ----
        const uint4 w2h0 = sW2H[0][lane], w2h1 = sW2H[1][lane];
        const uint4 w2l0 = sW2L[0][lane], w2l1 = sW2L[1][lane];

        float d2f[2][4];
        {
            float d0 = 0.f, dd1 = 0.f, d2 = 0.f, d3 = 0.f;
            mma_bf16(d0,dd1,d2,d3, hh[0][0],hh[0][1],hh[1][0],hh[1][1], w2h0.x, w2h0.y);
            mma_bf16(d0,dd1,d2,d3, hh[0][0],hh[0][1],hh[1][0],hh[1][1], w2l0.x, w2l0.y);
            mma_bf16(d0,dd1,d2,d3, hl[0][0],hl[0][1],hl[1][0],hl[1][1], w2h0.x, w2h0.y);
            mma_bf16(d0,dd1,d2,d3, hh[2][0],hh[2][1],hh[3][0],hh[3][1], w2h1.x, w2h1.y);
            mma_bf16(d0,dd1,d2,d3, hh[2][0],hh[2][1],hh[3][0],hh[3][1], w2l1.x, w2l1.y);
            mma_bf16(d0,dd1,d2,d3, hl[2][0],hl[2][1],hl[3][0],hl[3][1], w2h1.x, w2h1.y);
            d2f[0][0] = d0; d2f[0][1] = dd1; d2f[0][2] = d2; d2f[0][3] = d3;
            d0 = 0.f; dd1 = 0.f; d2 = 0.f; d3 = 0.f;
            mma_bf16(d0,dd1,d2,d3, hh[0][0],hh[0][1],hh[1][0],hh[1][1], w2h0.z, w2h0.w);
            mma_bf16(d0,dd1,d2,d3, hh[0][0],hh[0][1],hh[1][0],hh[1][1], w2l0.z, w2l0.w);
            mma_bf16(d0,dd1,d2,d3, hl[0][0],hl[0][1],hl[1][0],hl[1][1], w2h0.z, w2h0.w);
            mma_bf16(d0,dd1,d2,d3, hh[2][0],hh[2][1],hh[3][0],hh[3][1], w2h1.z, w2h1.w);
            mma_bf16(d0,dd1,d2,d3, hh[2][0],hh[2][1],hh[3][0],hh[3][1], w2l1.z, w2l1.w);
            mma_bf16(d0,dd1,d2,d3, hl[2][0],hl[2][1],hl[3][0],hl[3][1], w2h1.z, w2h1.w);
            d2f[1][0] = d0; d2f[1][1] = dd1; d2f[1][2] = d2; d2f[1][3] = d3;
        }

        // ---- LN2 ----
        u64 ss2 = 0ull, qq2 = 0ull;
        #pragma unroll
        for (int nb2 = 0; nb2 < 2; nb2++) {
            const u64 m0 = pk2(d2f[nb2][0], d2f[nb2][2]);
            const u64 m1 = pk2(d2f[nb2][1], d2f[nb2][3]);
            ss2 = add2(ss2, add2(m0, m1));
            qq2 = fma2(m0, m0, fma2(m1, m1, qq2));
        }
        ss2 = add2(ss2, shflx(ss2, 1)); ss2 = add2(ss2, shflx(ss2, 2));
        qq2 = add2(qq2, shflx(qq2, 1)); qq2 = add2(qq2, shflx(qq2, 2));
        float2 sv2 = upk2(ss2), qv2 = upk2(qq2);
        const float m2A = sv2.x * (1.0f/16.0f), m2B = sv2.y * (1.0f/16.0f);
        const float s2A = rsqrtf(qv2.x * (1.0f/16.0f) - m2A * m2A + 1e-5f);
        const float s2B = rsqrtf(qv2.y * (1.0f/16.0f) - m2B * m2B + 1e-5f);
        const u64 sc2pA = pk2(s2A, s2A), nm2pA = pk2(-m2A*s2A, -m2A*s2A);
        const u64 sc2pB = pk2(s2B, s2B), nm2pB = pk2(-m2B*s2B, -m2B*s2B);

        const ulonglong2 g2q = sG2[lane], b2q = sB2[lane];
        const u64 g2p[2] = {g2q.x, g2q.y};
        const u64 b2p[2] = {b2q.x, b2q.y};

        u32 h2h[2][2], h2l[2][2];
        #pragma unroll
        for (int nb2 = 0; nb2 < 2; nb2++) {
            u64 u0 = fma2(fma2(pk2(d2f[nb2][0], d2f[nb2][1]), sc2pA, nm2pA), g2p[nb2], b2p[nb2]);
            u64 u1 = fma2(fma2(pk2(d2f[nb2][2], d2f[nb2][3]), sc2pB, nm2pB), g2p[nb2], b2p[nb2]);
            float2 f0 = upk2(u0), f1 = upk2(u1);
            split2(fmaxf(f0.x, 0.f), fmaxf(f0.y, 0.f), h2h[nb2][0], h2l[nb2][0]);
            split2(fmaxf(f1.x, 0.f), fmaxf(f1.y, 0.f), h2h[nb2][1], h2l[nb2][1]);
        }

        // ---- layer 3 on HMMA ----
        const uint4 w3q = sW3F[lane];
        float e0 = 0.f, e1 = 0.f, e2 = 0.f, e3 = 0.f;
        mma_bf16(e0,e1,e2,e3, h2h[0][0],h2h[0][1],h2h[1][0],h2h[1][1], w3q.x, w3q.y);
        mma_bf16(e0,e1,e2,e3, h2h[0][0],h2h[0][1],h2h[1][0],h2h[1][1], w3q.z, w3q.w);
        mma_bf16(e0,e1,e2,e3, h2l[0][0],h2l[0][1],h2l[1][0],h2l[1][1], w3q.x, w3q.y);

        // ---- gather channel 2 from quad neighbor, normalize, store ----
        const float c2A = __shfl_down_sync(0xffffffffu, e0, 1);
        const float c2B = __shfl_down_sync(0xffffffffu, e2, 1);
        if (t == 0) {
            {
                const int row = R + g;
                if (row < N) {
                    const float o0 = e0 + bb0, o1 = e1 + bb1, o2 = c2A + bb2;
                    const float inv = 1.0f / fmaxf(sqrtf(o0*o0 + o1*o1 + o2*o2), 1e-12f);
                    const int b  = row / HW;
                    const int hw = row - b * HW;
                    const int ob = (b * 3) * HW + hw;
                    out[ob] = o0 * inv; out[ob + HW] = o1 * inv; out[ob + 2*HW] = o2 * inv;
                }
            }
            {
                const int row = R + g + 8;
                if (row < N) {
                    const float o0 = e2 + bb0, o1 = e3 + bb1, o2 = c2B + bb2;
                    const float inv = 1.0f / fmaxf(sqrtf(o0*o0 + o1*o1 + o2*o2), 1e-12f);
                    const int b  = row / HW;
                    const int hw = row - b * HW;
                    const int ob = (b * 3) * HW + hw;
                    out[ob] = o0 * inv; out[ob + HW] = o1 * inv; out[ob + 2*HW] = o2 * inv;
                }
            }
        }
    }
}

extern "C" void kernel_launch(void* const* d_in, const int* in_sizes, int n_in,
                              void* d_out, int out_size)
{
    const float* x  = (const float*)d_in[0];
    const float* w1 = (const float*)d_in[1];
    const float* g1 = (const float*)d_in[2];
    const float* b1 = (const float*)d_in[3];
    const float* w2 = (const float*)d_in[4];
    const float* g2 = (const float*)d_in[5];
    const float* b2 = (const float*)d_in[6];
    const float* w3 = (const float*)d_in[7];
    const float* b3 = (const float*)d_in[8];
    const int*   Bp = (const int*)d_in[9];

    const int N       = in_sizes[0] / 64;
    const int ngroups = (N + 15) / 16;
    int blocks = (ngroups + 3) / 4;
    if (blocks > NCTAS) blocks = NCTAS;

    fused_decoder_frag<<<blocks, TPB>>>(
        x, w1, g1, b1, w2, g2, b2, w3, b3, Bp,
        (float*)d_out, N, ngroups);
}

// round 10
// speedup vs baseline: 3.8039x; 1.0658x over previous
#include <cuda_runtime.h>
#include <cuda_bf16.h>

typedef unsigned long long u64;
typedef unsigned int u32;

// ---------------- packed f32x2 helpers ----------------
__device__ __forceinline__ u64 pk2(float lo, float hi) {
    u64 r; asm("mov.b64 %0,{%1,%2};" : "=l"(r) : "f"(lo), "f"(hi)); return r;
}
__device__ __forceinline__ float2 upk2(u64 v) {
    float2 f; asm("mov.b64 {%0,%1},%2;" : "=f"(f.x), "=f"(f.y) : "l"(v)); return f;
}
__device__ __forceinline__ u64 fma2(u64 a, u64 b, u64 c) {
    u64 d; asm("fma.rn.f32x2 %0,%1,%2,%3;" : "=l"(d) : "l"(a), "l"(b), "l"(c)); return d;
}
__device__ __forceinline__ u64 add2(u64 a, u64 b) {
    u64 d; asm("add.rn.f32x2 %0,%1,%2;" : "=l"(d) : "l"(a), "l"(b)); return d;
}

// ---------------- HMMA m16n8k16 row.col f32.bf16.bf16.f32 ----------------
__device__ __forceinline__ void mma_bf16(float& d0, float& d1, float& d2, float& d3,
                                         u32 a0, u32 a1, u32 a2, u32 a3,
                                         u32 b0, u32 b1) {
    asm volatile(
        "mma.sync.aligned.m16n8k16.row.col.f32.bf16.bf16.f32 "
        "{%0,%1,%2,%3}, {%4,%5,%6,%7}, {%8,%9}, {%0,%1,%2,%3};"
        : "+f"(d0), "+f"(d1), "+f"(d2), "+f"(d3)
        : "r"(a0), "r"(a1), "r"(a2), "r"(a3), "r"(b0), "r"(b1));
}

// two floats -> bf16x2 hi + bf16x2 residual lo (bit-op reconstruction + packed fma)
__device__ __forceinline__ void split2(float v0, float v1, u32& h, u32& l) {
    __nv_bfloat162 hb = __float22bfloat162_rn(make_float2(v0, v1));
    h = *reinterpret_cast<u32*>(&hb);
    const float f0 = __uint_as_float(h << 16);
    const float f1 = __uint_as_float(h & 0xffff0000u);
    const u64 r = fma2(pk2(f0, f1), 0xBF800000BF800000ull /*(-1,-1)*/, pk2(v0, v1));
    const float2 rf = upk2(r);
    __nv_bfloat162 lb = __float22bfloat162_rn(make_float2(rf.x, rf.y));
    l = *reinterpret_cast<u32*>(&lb);
}

__device__ __forceinline__ u64 shflx(u64 v, int m) {
    return (u64)__shfl_xor_sync(0xffffffffu, (unsigned long long)v, m);
}

#define TPB    128
#define NCTAS  592   // 148 SM * 4

// raw x loads for one 16-row group (k-permuted: lane quad t reads cols [4t,4t+3])
__device__ __forceinline__ void load_x(const float* __restrict__ x, int R, int g, int t,
                                       int N, float4 q0[4], float4 q1[4]) {
    int r0 = R + g;     if (r0 > N - 1) r0 = N - 1;
    int r1 = R + g + 8; if (r1 > N - 1) r1 = N - 1;
    const float4* p0 = (const float4*)(x + (size_t)r0 * 64 + 4 * t);
    const float4* p1 = (const float4*)(x + (size_t)r1 * 64 + 4 * t);
    #pragma unroll
    for (int kb = 0; kb < 4; kb++) { q0[kb] = p0[kb * 4]; q1[kb] = p1[kb * 4]; }
}

__global__ __launch_bounds__(TPB, 4)
void fused_decoder_frag(const float* __restrict__ x,
                        const float* __restrict__ w1,
                        const float* __restrict__ g1v,
                        const float* __restrict__ b1v,
                        const float* __restrict__ w2,
                        const float* __restrict__ g2v,
                        const float* __restrict__ b2v,
                        const float* __restrict__ w3,
                        const float* __restrict__ b3,
                        const int*   __restrict__ Bp,
                        float*       __restrict__ out,
                        int N, int ngroups)
{
    // w1 B-fragments (bf16 hi/lo), mma layout: [kb*4+nb][lane] = {b0,b1}
    __shared__ __align__(16) uint2 sBH[16][32];
    __shared__ __align__(16) uint2 sBL[16][32];
    // per-lane constant fragment images
    __shared__ __align__(16) uint4      sW2H[2][32];
    __shared__ __align__(16) uint4      sW2L[2][32];
    __shared__ __align__(16) uint4      sW3F[32];
    __shared__ __align__(16) ulonglong2 sG1[2][32];
    __shared__ __align__(16) ulonglong2 sB1[2][32];
    __shared__ __align__(16) ulonglong2 sG2[32];
    __shared__ __align__(16) ulonglong2 sB2[32];
    __shared__ float sb3s[3];

    const int tid  = threadIdx.x;
    const int wid  = tid >> 5;
    const int lane = tid & 31;
    const int g    = lane >> 2;        // row-in-group 0..7
    const int t    = lane & 3;         // col-quad selector

    // ---- one-time: stage w1 B-frags with the k permutation baked in ----
    for (int e = tid; e < 512; e += TPB) {
        const int kn = e >> 5, l = e & 31;
        const int kb = kn >> 2, nb = kn & 3;
        const int c4 = (l & 3) * 4;
        const int gg = l >> 2;
        const int col  = nb * 8 + gg;
        const int krow = kb * 16 + c4;
        u32 h01, l01, h23, l23;
        split2(w1[(krow + 0) * 32 + col], w1[(krow + 1) * 32 + col], h01, l01);
        split2(w1[(krow + 2) * 32 + col], w1[(krow + 3) * 32 + col], h23, l23);
        sBH[kn][l] = make_uint2(h01, h23);
        sBL[kn][l] = make_uint2(l01, l23);
    }

    // ---- one-time: per-lane constant images (warp 0 computes) ----
    if (wid == 0) {
        #pragma unroll
        for (int kb2 = 0; kb2 < 2; kb2++) {
            const int k0 = kb2 * 16 + 2 * t;
            u32 h00, l00, h01_, l01_, h10, l10, h11, l11;
            split2(w2[k0 * 16 + g],           w2[(k0 + 1) * 16 + g],           h00, l00);
            split2(w2[(k0 + 8) * 16 + g],     w2[(k0 + 9) * 16 + g],           h01_, l01_);
            split2(w2[k0 * 16 + 8 + g],       w2[(k0 + 1) * 16 + 8 + g],       h10, l10);
            split2(w2[(k0 + 8) * 16 + 8 + g], w2[(k0 + 9) * 16 + 8 + g],       h11, l11);
            sW2H[kb2][lane] = make_uint4(h00, h01_, h10, h11);
            sW2L[kb2][lane] = make_uint4(l00, l01_, l10, l11);
        }
        {
            u32 wh0 = 0u, wh1 = 0u, wl0 = 0u, wl1 = 0u;
            if (g < 3) {
                const int k0 = 2 * t;
                split2(w3[k0 * 3 + g],       w3[(k0 + 1) * 3 + g], wh0, wl0);
                split2(w3[(k0 + 8) * 3 + g], w3[(k0 + 9) * 3 + g], wh1, wl1);
            }
            sW3F[lane] = make_uint4(wh0, wh1, wl0, wl1);
        }
        {
            u64 gp[4], bp[4];
            #pragma unroll
            for (int nb = 0; nb < 4; nb++) {
                const int c0 = nb * 8 + 2 * t;
                gp[nb] = pk2(g1v[c0], g1v[c0 + 1]);
                bp[nb] = pk2(b1v[c0], b1v[c0 + 1]);
            }
            sG1[0][lane] = make_ulonglong2(gp[0], gp[1]);
            sG1[1][lane] = make_ulonglong2(gp[2], gp[3]);
            sB1[0][lane] = make_ulonglong2(bp[0], bp[1]);
            sB1[1][lane] = make_ulonglong2(bp[2], bp[3]);
            sG2[lane] = make_ulonglong2(pk2(g2v[2*t], g2v[2*t+1]), pk2(g2v[8+2*t], g2v[8+2*t+1]));
            sB2[lane] = make_ulonglong2(pk2(b2v[2*t], b2v[2*t+1]), pk2(b2v[8+2*t], b2v[8+2*t+1]));
        }
        if (lane < 3) sb3s[lane] = b3[lane];
    }
    __syncthreads();

    const int Bv = __ldg(Bp);
    const int HW = N / Bv;
    const float bb0 = sb3s[0], bb1 = sb3s[1], bb2 = sb3s[2];

    const int gw0    = blockIdx.x * 4 + wid;
    const int nwarps = gridDim.x * 4;

    // ---- software pipeline: loads for group i+1 fly while group i computes ----
    int grp = gw0;
    float4 q0[4], q1[4];
    if (grp < ngroups) load_x(x, grp * 16, g, t, N, q0, q1);

    #pragma unroll 1
    while (grp < ngroups) {
        const int R   = grp * 16;
        const int nxt = grp + nwarps;

        // ---- split current loads into A-frags (frees q regs for the prefetch) ----
        u32 ah[4][4], al[4][4];
        #pragma unroll
        for (int kb = 0; kb < 4; kb++) {
            split2(q0[kb].x, q0[kb].y, ah[kb][0], al[kb][0]);
            split2(q1[kb].x, q1[kb].y, ah[kb][1], al[kb][1]);
            split2(q0[kb].z, q0[kb].w, ah[kb][2], al[kb][2]);
            split2(q1[kb].z, q1[kb].w, ah[kb][3], al[kb][3]);
        }

        // ---- issue next group's loads NOW; they complete during compute below ----
        if (nxt < ngroups) load_x(x, nxt * 16, g, t, N, q0, q1);

        // ---- layer 1: 4 n-blocks on HMMA ----
        float d1[4][4];
        #pragma unroll
        for (int nb = 0; nb < 4; nb++) {
            float d0 = 0.f, dd1 = 0.f, d2 = 0.f, d3 = 0.f;
            #pragma unroll
            for (int kb = 0; kb < 4; kb++) {
                const uint2 bh = sBH[kb * 4 + nb][lane];
                const uint2 bl = sBL[kb * 4 + nb][lane];
                mma_bf16(d0,dd1,d2,d3, ah[kb][0],ah[kb][1],ah[kb][2],ah[kb][3], bh.x, bh.y);
                mma_bf16(d0,dd1,d2,d3, ah[kb][0],ah[kb][1],ah[kb][2],ah[kb][3], bl.x, bl.y);
                mma_bf16(d0,dd1,d2,d3, al[kb][0],al[kb][1],al[kb][2],al[kb][3], bh.x, bh.y);
            }
            d1[nb][0] = d0; d1[nb][1] = dd1; d1[nb][2] = d2; d1[nb][3] = d3;
        }

        // ---- LN1 in frag layout: quad shuffle stats ----
        u64 ss = 0ull, qq = 0ull;
        #pragma unroll
        for (int nb = 0; nb < 4; nb++) {
            const u64 m0 = pk2(d1[nb][0], d1[nb][2]);
            const u64 m1 = pk2(d1[nb][1], d1[nb][3]);
            ss = add2(ss, add2(m0, m1));
            qq = fma2(m0, m0, fma2(m1, m1, qq));
        }
        ss = add2(ss, shflx(ss, 1)); ss = add2(ss, shflx(ss, 2));
        qq = add2(qq, shflx(qq, 1)); qq = add2(qq, shflx(qq, 2));
        float2 sv = upk2(ss), qv = upk2(qq);
        const float mgA = sv.x * (1.0f/32.0f), mgB = sv.y * (1.0f/32.0f);
        const float scA = rsqrtf(qv.x * (1.0f/32.0f) - mgA * mgA + 1e-5f);
        const float scB = rsqrtf(qv.y * (1.0f/32.0f) - mgB * mgB + 1e-5f);
        const u64 scpA = pk2(scA, scA), nmpA = pk2(-mgA*scA, -mgA*scA);
        const u64 scpB = pk2(scB, scB), nmpB = pk2(-mgB*scB, -mgB*scB);

        const ulonglong2 g1a = sG1[0][lane], g1b = sG1[1][lane];
        const ulonglong2 b1a = sB1[0][lane], b1b = sB1[1][lane];
        const u64 g1p[4] = {g1a.x, g1a.y, g1b.x, g1b.y};
        const u64 b1p[4] = {b1a.x, b1a.y, b1b.x, b1b.y};

        u32 hh[4][2], hl[4][2];
        #pragma unroll
        for (int nb = 0; nb < 4; nb++) {
            u64 u0 = fma2(fma2(pk2(d1[nb][0], d1[nb][1]), scpA, nmpA), g1p[nb], b1p[nb]);
            u64 u1 = fma2(fma2(pk2(d1[nb][2], d1[nb][3]), scpB, nmpB), g1p[nb], b1p[nb]);
            float2 f0 = upk2(u0), f1 = upk2(u1);
            split2(fmaxf(f0.x, 0.f), fmaxf(f0.y, 0.f), hh[nb][0], hl[nb][0]);
            split2(fmaxf(f1.x, 0.f), fmaxf(f1.y, 0.f), hh[nb][1], hl[nb][1]);
        }

        // ---- layer 2 on HMMA (w2 frags from smem) ----
        const uint4 w2h0 = sW2H[0][lane], w2h1 = sW2H[1][lane];
        const uint4 w2l0 = sW2L[0][lane], w2l1 = sW2L[1][lane];

        float d2f[2][4];
        {
            float d0 = 0.f, dd1 = 0.f, d2 = 0.f, d3 = 0.f;
            mma_bf16(d0,dd1,d2,d3, hh[0][0],hh[0][1],hh[1][0],hh[1][1], w2h0.x, w2h0.y);
            mma_bf16(d0,dd1,d2,d3, hh[0][0],hh[0][1],hh[1][0],hh[1][1], w2l0.x, w2l0.y);
            mma_bf16(d0,dd1,d2,d3, hl[0][0],hl[0][1],hl[1][0],hl[1][1], w2h0.x, w2h0.y);
            mma_bf16(d0,dd1,d2,d3, hh[2][0],hh[2][1],hh[3][0],hh[3][1], w2h1.x, w2h1.y);
            mma_bf16(d0,dd1,d2,d3, hh[2][0],hh[2][1],hh[3][0],hh[3][1], w2l1.x, w2l1.y);
            mma_bf16(d0,dd1,d2,d3, hl[2][0],hl[2][1],hl[3][0],hl[3][1], w2h1.x, w2h1.y);
            d2f[0][0] = d0; d2f[0][1] = dd1; d2f[0][2] = d2; d2f[0][3] = d3;
            d0 = 0.f; dd1 = 0.f; d2 = 0.f; d3 = 0.f;
            mma_bf16(d0,dd1,d2,d3, hh[0][0],hh[0][1],hh[1][0],hh[1][1], w2h0.z, w2h0.w);
            mma_bf16(d0,dd1,d2,d3, hh[0][0],hh[0][1],hh[1][0],hh[1][1], w2l0.z, w2l0.w);
            mma_bf16(d0,dd1,d2,d3, hl[0][0],hl[0][1],hl[1][0],hl[1][1], w2h0.z, w2h0.w);
            mma_bf16(d0,dd1,d2,d3, hh[2][0],hh[2][1],hh[3][0],hh[3][1], w2h1.z, w2h1.w);
            mma_bf16(d0,dd1,d2,d3, hh[2][0],hh[2][1],hh[3][0],hh[3][1], w2l1.z, w2l1.w);
            mma_bf16(d0,dd1,d2,d3, hl[2][0],hl[2][1],hl[3][0],hl[3][1], w2h1.z, w2h1.w);
            d2f[1][0] = d0; d2f[1][1] = dd1; d2f[1][2] = d2; d2f[1][3] = d3;
        }

        // ---- LN2 ----
        u64 ss2 = 0ull, qq2 = 0ull;
        #pragma unroll
        for (int nb2 = 0; nb2 < 2; nb2++) {
            const u64 m0 = pk2(d2f[nb2][0], d2f[nb2][2]);
            const u64 m1 = pk2(d2f[nb2][1], d2f[nb2][3]);
            ss2 = add2(ss2, add2(m0, m1));
            qq2 = fma2(m0, m0, fma2(m1, m1, qq2));
        }
        ss2 = add2(ss2, shflx(ss2, 1)); ss2 = add2(ss2, shflx(ss2, 2));
        qq2 = add2(qq2, shflx(qq2, 1)); qq2 = add2(qq2, shflx(qq2, 2));
        float2 sv2 = upk2(ss2), qv2 = upk2(qq2);
        const float m2A = sv2.x * (1.0f/16.0f), m2B = sv2.y * (1.0f/16.0f);
        const float s2A = rsqrtf(qv2.x * (1.0f/16.0f) - m2A * m2A + 1e-5f);
        const float s2B = rsqrtf(qv2.y * (1.0f/16.0f) - m2B * m2B + 1e-5f);
        const u64 sc2pA = pk2(s2A, s2A), nm2pA = pk2(-m2A*s2A, -m2A*s2A);
        const u64 sc2pB = pk2(s2B, s2B), nm2pB = pk2(-m2B*s2B, -m2B*s2B);

        const ulonglong2 g2q = sG2[lane], b2q = sB2[lane];
        const u64 g2p[2] = {g2q.x, g2q.y};
        const u64 b2p[2] = {b2q.x, b2q.y};

        u32 h2h[2][2], h2l[2][2];
        #pragma unroll
        for (int nb2 = 0; nb2 < 2; nb2++) {
            u64 u0 = fma2(fma2(pk2(d2f[nb2][0], d2f[nb2][1]), sc2pA, nm2pA), g2p[nb2], b2p[nb2]);
            u64 u1 = fma2(fma2(pk2(d2f[nb2][2], d2f[nb2][3]), sc2pB, nm2pB), g2p[nb2], b2p[nb2]);
            float2 f0 = upk2(u0), f1 = upk2(u1);
            split2(fmaxf(f0.x, 0.f), fmaxf(f0.y, 0.f), h2h[nb2][0], h2l[nb2][0]);
            split2(fmaxf(f1.x, 0.f), fmaxf(f1.y, 0.f), h2h[nb2][1], h2l[nb2][1]);
        }

        // ---- layer 3 on HMMA ----
        const uint4 w3q = sW3F[lane];
        float e0 = 0.f, e1 = 0.f, e2 = 0.f, e3 = 0.f;
        mma_bf16(e0,e1,e2,e3, h2h[0][0],h2h[0][1],h2h[1][0],h2h[1][1], w3q.x, w3q.y);
        mma_bf16(e0,e1,e2,e3, h2h[0][0],h2h[0][1],h2h[1][0],h2h[1][1], w3q.z, w3q.w);
        mma_bf16(e0,e1,e2,e3, h2l[0][0],h2l[0][1],h2l[1][0],h2l[1][1], w3q.x, w3q.y);

        // ---- gather channel 2 from quad neighbor, normalize, store ----
        const float c2A = __shfl_down_sync(0xffffffffu, e0, 1);
        const float c2B = __shfl_down_sync(0xffffffffu, e2, 1);
        if (t == 0) {
            {
                const int row = R + g;
                if (row < N) {
                    const float o0 = e0 + bb0, o1 = e1 + bb1, o2 = c2A + bb2;
                    const float inv = 1.0f / fmaxf(sqrtf(o0*o0 + o1*o1 + o2*o2), 1e-12f);
                    const int b  = row / HW;
                    const int hw = row - b * HW;
                    const int ob = (b * 3) * HW + hw;
                    out[ob] = o0 * inv; out[ob + HW] = o1 * inv; out[ob + 2*HW] = o2 * inv;
                }
            }
            {
                const int row = R + g + 8;
                if (row < N) {
                    const float o0 = e2 + bb0, o1 = e3 + bb1, o2 = c2B + bb2;
                    const float inv = 1.0f / fmaxf(sqrtf(o0*o0 + o1*o1 + o2*o2), 1e-12f);
                    const int b  = row / HW;
                    const int hw = row - b * HW;
                    const int ob = (b * 3) * HW + hw;
                    out[ob] = o0 * inv; out[ob + HW] = o1 * inv; out[ob + 2*HW] = o2 * inv;
                }
            }
        }

        grp = nxt;
    }
}

extern "C" void kernel_launch(void* const* d_in, const int* in_sizes, int n_in,
                              void* d_out, int out_size)
{
    const float* x  = (const float*)d_in[0];
    const float* w1 = (const float*)d_in[1];
    const float* g1 = (const float*)d_in[2];
    const float* b1 = (const float*)d_in[3];
    const float* w2 = (const float*)d_in[4];
    const float* g2 = (const float*)d_in[5];
    const float* b2 = (const float*)d_in[6];
    const float* w3 = (const float*)d_in[7];
    const float* b3 = (const float*)d_in[8];
    const int*   Bp = (const int*)d_in[9];

    const int N       = in_sizes[0] / 64;
    const int ngroups = (N + 15) / 16;
    int blocks = (ngroups + 3) / 4;
    if (blocks > NCTAS) blocks = NCTAS;

    fused_decoder_frag<<<blocks, TPB>>>(
        x, w1, g1, b1, w2, g2, b2, w3, b3, Bp,
        (float*)d_out, N, ngroups);
}